// round 14
// baseline (speedup 1.0000x reference)
#include <cuda_runtime.h>
#include <cuda_fp16.h>
#include <cstdint>

// ---------------- problem constants ----------------
#define B_  32
#define S_  512
#define H_  768
#define NH_ 12
#define DH_ 64
#define EC_ 4
#define EU_ 4
#define CAP_ 8   // int(1.0 * 32 / 4)

#define NELEM (B_ * S_ * H_)
#define LOG2E_ 1.4426950408889634f
#define QSCALE_ (0.125f * LOG2E_)

// ---------------- scratch (static device memory; no allocs) ----------------
__device__ float g_hmean[B_ * H_];
__device__ int   g_eidx[B_];
__device__ int   g_used[8];
__device__ __align__(16) __half g_hs_hi[NELEM];
__device__ __align__(16) __half g_q_hi[NELEM];
__device__ __align__(16) __half g_k_hi[NELEM];
__device__ __align__(16) __half g_v_hi[NELEM];
__device__ __align__(16) __half g_ctx_hi[NELEM];
// transposed expert weights (hi only): [mat(4)][e(8)][n(768)][k(768)]
#define WT_PER (8 * H_ * H_)
__device__ __align__(16) __half g_wt_hi[4 * WT_PER];

// ================= PTX helpers (baseline PTX only) =================
__device__ __forceinline__ uint32_t smem_u32(const void* p) {
    uint32_t a;
    asm("{ .reg .u64 t; cvta.to.shared.u64 t, %1; cvt.u32.u64 %0, t; }" : "=r"(a) : "l"(p));
    return a;
}

__device__ __forceinline__ void cp16(uint32_t saddr, const void* gaddr) {
    asm volatile("cp.async.cg.shared.global [%0], [%1], 16;" :: "r"(saddr), "l"(gaddr));
}
#define CP_COMMIT() asm volatile("cp.async.commit_group;" ::: "memory")
#define CP_WAIT1()  asm volatile("cp.async.wait_group 1;" ::: "memory")
#define CP_WAIT0()  asm volatile("cp.async.wait_group 0;" ::: "memory")

#define LDSM_X4(r, addr) \
    asm volatile("ldmatrix.sync.aligned.m8n8.x4.shared.b16 {%0,%1,%2,%3}, [%4];" \
        : "=r"((r)[0]), "=r"((r)[1]), "=r"((r)[2]), "=r"((r)[3]) : "r"(addr))

#define LDSM_X4_T(r, addr) \
    asm volatile("ldmatrix.sync.aligned.m8n8.x4.trans.shared.b16 {%0,%1,%2,%3}, [%4];" \
        : "=r"((r)[0]), "=r"((r)[1]), "=r"((r)[2]), "=r"((r)[3]) : "r"(addr))

#define MMA_F16(c, a, bb) \
    asm volatile("mma.sync.aligned.m16n8k16.row.col.f32.f16.f16.f32 " \
        "{%0,%1,%2,%3}, {%4,%5,%6,%7}, {%8,%9}, {%0,%1,%2,%3};" \
        : "+f"((c)[0]), "+f"((c)[1]), "+f"((c)[2]), "+f"((c)[3]) \
        : "r"((a)[0]), "r"((a)[1]), "r"((a)[2]), "r"((a)[3]), "r"((bb)[0]), "r"((bb)[1]))

__device__ __forceinline__ uint32_t packh(float lo, float hi) {
    uint32_t r;
    asm("cvt.rn.f16x2.f32 %0, %1, %2;" : "=r"(r) : "f"(hi), "f"(lo));
    return r;
}
__device__ __forceinline__ float ex2f(float x) {
    float y;
    asm("ex2.approx.ftz.f32 %0, %1;" : "=f"(y) : "f"(x));
    return y;
}

// ---------------- 1) mean over sequence + fp16 rounding of hs (fused) ----------------
__global__ void mean_round_kernel(const float* __restrict__ hs, __half* __restrict__ hi) {
    const int b = blockIdx.x;
    const int h = threadIdx.x;                 // 768 threads
    const float* p = hs + (size_t)b * S_ * H_ + h;
    __half* q = hi + (size_t)b * S_ * H_ + h;
    float acc = 0.f;
    #pragma unroll 8
    for (int s = 0; s < S_; s++) {
        const float x = p[(size_t)s * H_];
        acc += x;
        q[(size_t)s * H_] = __float2half_rn(x);
    }
    g_hmean[b * H_ + h] = acc * (1.0f / S_);
}

// ---------------- 2) routing + capacity drop (256 threads: 8 per sequence) ----------------
__global__ void route_kernel(const float* __restrict__ Wsc, const float* __restrict__ bsc,
                             const float* __restrict__ Wsu, const float* __restrict__ bsu) {
    __shared__ float pcmax[B_];
    __shared__ int   rcs[B_];
    __shared__ int   rus[B_];
    const int tid = threadIdx.x;
    const int g = tid & 7;
    const int b = tid >> 3;
    if (tid < 8) g_used[tid] = 0;
    {
        float lc[EC_] = {}, lu[EU_] = {};
        for (int h = g; h < H_; h += 8) {
            float x = g_hmean[b * H_ + h];
            #pragma unroll
            for (int e = 0; e < EC_; e++) lc[e] += x * Wsc[h * EC_ + e];
            #pragma unroll
            for (int e = 0; e < EU_; e++) lu[e] += x * Wsu[h * EU_ + e];
        }
        #pragma unroll
        for (int m = 1; m < 8; m <<= 1) {
            #pragma unroll
            for (int e = 0; e < EC_; e++) lc[e] += __shfl_xor_sync(0xffffffffu, lc[e], m);
            #pragma unroll
            for (int e = 0; e < EU_; e++) lu[e] += __shfl_xor_sync(0xffffffffu, lu[e], m);
        }
        if (g == 0) {
            #pragma unroll
            for (int e = 0; e < EC_; e++) lc[e] += bsc[e];
            #pragma unroll
            for (int e = 0; e < EU_; e++) lu[e] += bsu[e];
            float mc = lc[0]; int rc = 0;
            #pragma unroll
            for (int e = 1; e < EC_; e++) if (lc[e] > mc) { mc = lc[e]; rc = e; }
            float sc = 0.f;
            #pragma unroll
            for (int e = 0; e < EC_; e++) sc += __expf(lc[e] - mc);
            float mu = lu[0]; int ru = 0;
            #pragma unroll
            for (int e = 1; e < EU_; e++) if (lu[e] > mu) { mu = lu[e]; ru = e; }
            pcmax[b] = 1.f / sc;
            rcs[b] = rc;
            rus[b] = ru;
        }
    }
    __syncthreads();
    if (tid < B_) {
        const int b2i = tid;
        int rank = 1;
        const float pm = pcmax[b2i];
        const int   rc = rcs[b2i];
        for (int b2 = 0; b2 < B_; b2++) {
            if (b2 == b2i || rcs[b2] != rc) continue;
            if (pcmax[b2] > pm || (pcmax[b2] == pm && b2 < b2i)) rank++;
        }
        const int ei = (rank <= CAP_) ? rc : (EC_ + rus[b2i]);
        g_eidx[b2i] = ei;
        atomicExch(&g_used[ei], 1);
    }
}

// ---------------- prep: transpose used-expert W mats [e][k][n] -> Wt [mat][e][n][k], fp16 --------
__global__ void prep_w4_kernel(const float* __restrict__ W0, const float* __restrict__ W1,
                               const float* __restrict__ W2, const float* __restrict__ W3,
                               __half* __restrict__ th) {
    __shared__ float tile[32][33];
    const int mz = blockIdx.z;
    const int mat = mz >> 3, e = mz & 7;
    if (!g_used[e]) return;
    const int n0 = blockIdx.x * 32;
    const int k0 = blockIdx.y * 32;
    const int tx = threadIdx.x, ty = threadIdx.y;   // 32 x 8
    const float* W = (mat == 0 ? W0 : mat == 1 ? W1 : mat == 2 ? W2 : W3);
    const float* We = W + (size_t)e * H_ * H_;
    __half* to = th + (size_t)mat * WT_PER + (size_t)e * H_ * H_;
    #pragma unroll
    for (int j = 0; j < 32; j += 8)
        tile[ty + j][tx] = We[(size_t)(k0 + ty + j) * H_ + n0 + tx];
    __syncthreads();
    #pragma unroll
    for (int j = 0; j < 32; j += 8) {
        float x = tile[tx][ty + j];
        to[(size_t)(n0 + ty + j) * H_ + k0 + tx] = __float2half_rn(x);
    }
}

// ================ core GEMM tile routine (1-term fp16, 3-stage BK=64, CTA 256x128) ================
// 8 warps as 4(M) x 2(N); warp tile 64x64. Stage (144B rows):
//   A [0, 36864) = 256 rows x 144B, B [36864, 55296) = 128 rows x 144B. 3 stages.
#define GST    55296
#define GB_OFF 36864
#define KIT    (H_ / 64)        // 12
#define GEMM_SMEM (3 * GST)     // 165888

struct GemmAcc { float a[4][8][4]; };   // [mt(4 x 16rows)][nt(8 x 8cols)][frag]

__device__ __forceinline__ void gemm_tile_body(
    uint32_t sbase, const __half* Ah, const __half* Wh, int tid, GemmAcc& G) {
    const int lane = tid & 31, wid = tid >> 5;
    const int warp_m = (wid & 3) * 64, warp_n = (wid >> 2) * 64;

    auto issue = [&](int kc) {
        const uint32_t sb = sbase + (uint32_t)(kc % 3) * GST;
        const int k0 = kc * 64;
        #pragma unroll
        for (int i = 0; i < 8; i++) {
            const int idx = i * 256 + tid;
            const int row = idx >> 3, c = idx & 7;
            cp16(sb + row * 144 + c * 16, Ah + (size_t)row * H_ + k0 + c * 8);
        }
        #pragma unroll
        for (int i = 0; i < 4; i++) {
            const int idx = i * 256 + tid;
            const int row = idx >> 3, c = idx & 7;
            cp16(sb + GB_OFF + row * 144 + c * 16, Wh + (size_t)row * H_ + k0 + c * 8);
        }
        CP_COMMIT();
    };

    issue(0);
    issue(1);
    for (int kc = 0; kc < KIT; kc++) {
        if (kc < KIT - 1) { CP_WAIT1(); } else { CP_WAIT0(); }
        __syncthreads();
        if (kc + 2 < KIT) issue(kc + 2);
        const uint32_t sb = sbase + (uint32_t)(kc % 3) * GST;
        #pragma unroll
        for (int ks = 0; ks < 64; ks += 16) {
            uint32_t bh[4][4], ah[4][4];
            #pragma unroll
            for (int p = 0; p < 4; p++) {
                const uint32_t addr = sb + GB_OFF +
                    (uint32_t)((warp_n + p * 16 + (lane >> 4) * 8 + (lane & 7)) * 144 +
                               (ks + ((lane >> 3) & 1) * 8) * 2);
                LDSM_X4(bh[p], addr);
            }
            #pragma unroll
            for (int mt = 0; mt < 4; mt++) {
                const uint32_t addr = sb +
                    (uint32_t)((warp_m + mt * 16 + (lane & 15)) * 144 +
                               (ks + (lane >> 4) * 8) * 2);
                LDSM_X4(ah[mt], addr);
            }
            #pragma unroll
            for (int mt = 0; mt < 4; mt++) {
                #pragma unroll
                for (int nt = 0; nt < 8; nt++) {
                    uint32_t* bhp = &bh[nt >> 1][(nt & 1) * 2];
                    MMA_F16(G.a[mt][nt], ah[mt], bhp);
                }
            }
        }
    }
}

// ---------------- fused QKV projection: 3 mats in one launch ----------------
// grid (18, 2, 32): mat = bx/6, n0 = (bx%6)*128; bm = by*256
__global__ __launch_bounds__(256, 1) void gemm_qkv_kernel(
    const __half* __restrict__ a_hi, const __half* __restrict__ w_all,
    const float* __restrict__ bq, const float* __restrict__ bk, const float* __restrict__ bv,
    __half* __restrict__ qout, __half* __restrict__ kout, __half* __restrict__ vout) {
    extern __shared__ char smem[];
    const uint32_t sbase = smem_u32(smem);
    const int tid = threadIdx.x;
    const int lane = tid & 31, wid = tid >> 5;
    const int mat = blockIdx.x / 6;
    const int n0  = (blockIdx.x % 6) * 128;
    const int b  = blockIdx.z;
    const int e  = g_eidx[b];
    const int bm = blockIdx.y * 256;
    const int warp_m = (wid & 3) * 64, warp_n = (wid >> 2) * 64;

    const float* bias = (mat == 0) ? bq : (mat == 1) ? bk : bv;
    __half* outp      = (mat == 0) ? qout : (mat == 1) ? kout : vout;
    const float scale = (mat == 0) ? QSCALE_ : 1.0f;

    const __half* Ah = a_hi + ((size_t)b * S_ + bm) * H_;
    const __half* Wh = w_all + (size_t)mat * WT_PER + ((size_t)e * H_ + n0) * H_;

    GemmAcc G = {};
    gemm_tile_body(sbase, Ah, Wh, tid, G);

    const int col_b = n0 + warp_n + (lane & 3) * 2;
    #pragma unroll
    for (int mt = 0; mt < 4; mt++) {
        const int r0 = bm + warp_m + mt * 16 + (lane >> 2);
        #pragma unroll
        for (int nt = 0; nt < 8; nt++) {
            const int cc = col_b + nt * 8;
            const float b0 = bias[e * H_ + cc];
            const float b1 = bias[e * H_ + cc + 1];
            float v00 = (G.a[mt][nt][0] + b0) * scale, v01 = (G.a[mt][nt][1] + b1) * scale;
            float v10 = (G.a[mt][nt][2] + b0) * scale, v11 = (G.a[mt][nt][3] + b1) * scale;
            const size_t o0 = ((size_t)b * S_ + r0) * H_ + cc;
            const size_t o1 = ((size_t)b * S_ + r0 + 8) * H_ + cc;
            *(uint32_t*)(outp + o0) = packh(v00, v01);
            *(uint32_t*)(outp + o1) = packh(v10, v11);
        }
    }
}

// ---------------- O projection (1-term, f32 out) ----------------
__global__ __launch_bounds__(256, 1) void gemm_o_kernel(
    const __half* __restrict__ a_hi, const __half* __restrict__ w_hi,
    const float* __restrict__ bias, float* __restrict__ C) {
    extern __shared__ char smem[];
    const uint32_t sbase = smem_u32(smem);
    const int tid = threadIdx.x;
    const int lane = tid & 31, wid = tid >> 5;
    const int b  = blockIdx.z;
    const int e  = g_eidx[b];
    const int n0 = blockIdx.x * 128;
    const int bm = blockIdx.y * 256;
    const int warp_m = (wid & 3) * 64, warp_n = (wid >> 2) * 64;

    const __half* Ah = a_hi + ((size_t)b * S_ + bm) * H_;
    const __half* Wh = w_hi + ((size_t)e * H_ + n0) * H_;

    GemmAcc G = {};
    gemm_tile_body(sbase, Ah, Wh, tid, G);

    float* Cb = C + (size_t)b * S_ * H_;
    const int col_b = n0 + warp_n + (lane & 3) * 2;
    #pragma unroll
    for (int mt = 0; mt < 4; mt++) {
        const int r0 = bm + warp_m + mt * 16 + (lane >> 2);
        #pragma unroll
        for (int nt = 0; nt < 8; nt++) {
            const int cc = col_b + nt * 8;
            const float b0 = bias[e * H_ + cc];
            const float b1 = bias[e * H_ + cc + 1];
            *(float2*)(Cb + (size_t)r0 * H_ + cc) =
                make_float2(G.a[mt][nt][0] + b0, G.a[mt][nt][1] + b1);
            *(float2*)(Cb + (size_t)(r0 + 8) * H_ + cc) =
                make_float2(G.a[mt][nt][2] + b0, G.a[mt][nt][3] + b1);
        }
    }
}

// ---------------- flash attention via mma.sync (fused QK->softmax->PV per key-chunk) ----------------
// Q pre-scaled by 0.125*log2e. Mask pre-scaled by log2e in smem. p = 2^(c + mask').
#define AT_STR 144                   // bytes per smem row
#define AT_TILE (128 * AT_STR)       // 18432 B
#define AT_QH 0
#define AT_KV AT_TILE                // per-buf: Kh, Vh
#define AT_BUF (2 * AT_TILE)
#define AT_MASK (AT_KV + 2 * AT_BUF) // 92160
#define ATTN_SMEM (AT_MASK + 2048)   // 94208

__global__ __launch_bounds__(256, 2) void attn_mma_kernel(
    const float* __restrict__ mask,
    const __half* __restrict__ qh_g,
    const __half* __restrict__ kh_g, const __half* __restrict__ vh_g,
    __half* __restrict__ ctx_hi) {
    extern __shared__ char smc[];
    const uint32_t sb = smem_u32(smc);
    const int tid = threadIdx.x;
    const int lane = tid & 31, w = tid >> 5;
    const int q0 = blockIdx.x * 128;
    const int hh = blockIdx.y;
    const int b  = blockIdx.z;
    const int r8 = lane & 7, g = lane >> 3;
    const float* mask_s = (const float*)(smc + AT_MASK);

    auto load_q = [&]() {
        #pragma unroll
        for (int i = 0; i < 4; i++) {
            const int idx = i * 256 + tid;
            const int row = idx >> 3, c16 = (idx & 7) * 16, ce = (idx & 7) * 8;
            const size_t ga = ((size_t)b * S_ + q0 + row) * H_ + hh * DH_ + ce;
            cp16(sb + AT_QH + row * AT_STR + c16, qh_g + ga);
        }
    };
    auto load_kv = [&](int t) {
        const uint32_t kb = sb + AT_KV + (t & 1) * AT_BUF;
        #pragma unroll
        for (int i = 0; i < 4; i++) {
            const int idx = i * 256 + tid;
            const int row = idx >> 3, c16 = (idx & 7) * 16, ce = (idx & 7) * 8;
            const size_t ga = ((size_t)b * S_ + t * 128 + row) * H_ + hh * DH_ + ce;
            const uint32_t so = row * AT_STR + c16;
            cp16(kb + so,           kh_g + ga);
            cp16(kb + AT_TILE + so, vh_g + ga);
        }
    };

    load_q(); load_kv(0); CP_COMMIT();
    load_kv(1); CP_COMMIT();
    if (tid < 128) {
        float4 m = *(const float4*)(mask + (size_t)b * S_ + tid * 4);
        *(float4*)(smc + AT_MASK + tid * 16) =
            make_float4(m.x * LOG2E_, m.y * LOG2E_, m.z * LOG2E_, m.w * LOG2E_);
    }

    uint32_t qh[4][4];
    float o[8][4] = {};
    float l1 = 0.f, l2 = 0.f;

    for (int t = 0; t < 4; t++) {
        if (t < 3) { CP_WAIT1(); } else { CP_WAIT0(); }
        __syncthreads();

        if (t == 0) {
            #pragma unroll
            for (int kc = 0; kc < 4; kc++) {
                const uint32_t qa = sb + (uint32_t)((w * 16 + (g & 1) * 8 + r8) * AT_STR +
                                                    (kc * 16 + (g >> 1) * 8) * 2);
                LDSM_X4(qh[kc], qa + AT_QH);
            }
        }

        const uint32_t kb = sb + AT_KV + (t & 1) * AT_BUF;
        #pragma unroll
        for (int np = 0; np < 8; np++) {
            float c0[4] = {}, c1[4] = {};
            #pragma unroll
            for (int kc = 0; kc < 4; kc++) {
                uint32_t bh[4];
                const uint32_t ka = kb + (uint32_t)((np * 16 + (g >> 1) * 8 + r8) * AT_STR +
                                                    (kc * 16 + (g & 1) * 8) * 2);
                LDSM_X4(bh, ka);
                MMA_F16(c0, qh[kc], bh);
                MMA_F16(c1, qh[kc], bh + 2);
            }
            uint32_t vf[4][4];
            #pragma unroll
            for (int nv = 0; nv < 4; nv++) {
                const uint32_t va = kb + AT_TILE +
                    (uint32_t)((np * 16 + (g & 1) * 8 + r8) * AT_STR +
                               (nv * 16 + (g >> 1) * 8) * 2);
                LDSM_X4_T(vf[nv], va);
            }
            const int key0 = t * 128 + np * 16 + 2 * (lane & 3);
            const float mk00 = mask_s[key0],     mk01 = mask_s[key0 + 1];
            const float mk10 = mask_s[key0 + 8], mk11 = mask_s[key0 + 9];
            c0[0] = ex2f(c0[0] + mk00); c0[1] = ex2f(c0[1] + mk01);
            c0[2] = ex2f(c0[2] + mk00); c0[3] = ex2f(c0[3] + mk01);
            c1[0] = ex2f(c1[0] + mk10); c1[1] = ex2f(c1[1] + mk11);
            c1[2] = ex2f(c1[2] + mk10); c1[3] = ex2f(c1[3] + mk11);
            l1 += c0[0] + c0[1] + c1[0] + c1[1];
            l2 += c0[2] + c0[3] + c1[2] + c1[3];
            uint32_t ph[4];
            ph[0] = packh(c0[0], c0[1]);
            ph[1] = packh(c0[2], c0[3]);
            ph[2] = packh(c1[0], c1[1]);
            ph[3] = packh(c1[2], c1[3]);
            #pragma unroll
            for (int nv = 0; nv < 4; nv++) {
                MMA_F16(o[2*nv],   ph, vf[nv]);
                MMA_F16(o[2*nv+1], ph, vf[nv] + 2);
            }
        }
        __syncthreads();
        if (t < 2) { load_kv(t + 2); CP_COMMIT(); }
    }

    // ---- epilogue ----
    l1 += __shfl_xor_sync(0xffffffffu, l1, 1);
    l1 += __shfl_xor_sync(0xffffffffu, l1, 2);
    l2 += __shfl_xor_sync(0xffffffffu, l2, 1);
    l2 += __shfl_xor_sync(0xffffffffu, l2, 2);
    const float inv1 = 1.f / l1, inv2 = 1.f / l2;
    const int row1 = q0 + w * 16 + (lane >> 2);
    #pragma unroll
    for (int nt = 0; nt < 8; nt++) {
        const int dh = hh * DH_ + nt * 8 + 2 * (lane & 3);
        const size_t o0 = ((size_t)b * S_ + row1) * H_ + dh;
        const size_t o1 = ((size_t)b * S_ + row1 + 8) * H_ + dh;
        *(uint32_t*)(ctx_hi + o0) = packh(o[nt][0] * inv1, o[nt][1] * inv1);
        *(uint32_t*)(ctx_hi + o1) = packh(o[nt][2] * inv2, o[nt][3] * inv2);
    }
}

// ---------------- launch ----------------
extern "C" void kernel_launch(void* const* d_in, const int* in_sizes, int n_in,
                              void* d_out, int out_size) {
    const float* hs   = (const float*)d_in[0];
    const float* mask = (const float*)d_in[1];
    const float* Wq = (const float*)d_in[2];
    const float* bq = (const float*)d_in[3];
    const float* Wk = (const float*)d_in[4];
    const float* bk = (const float*)d_in[5];
    const float* Wv = (const float*)d_in[6];
    const float* bv = (const float*)d_in[7];
    const float* Wo = (const float*)d_in[8];
    const float* bo = (const float*)d_in[9];
    const float* Wsc = (const float*)d_in[10];
    const float* bsc = (const float*)d_in[11];
    const float* Wsu = (const float*)d_in[12];
    const float* bsu = (const float*)d_in[13];
    float* out = (float*)d_out;

    void *phs_hi, *pq_hi, *pk_hi, *pv_hi, *pctx_hi, *pwt_hi;
    cudaGetSymbolAddress(&phs_hi, g_hs_hi);
    cudaGetSymbolAddress(&pq_hi, g_q_hi);
    cudaGetSymbolAddress(&pk_hi, g_k_hi);
    cudaGetSymbolAddress(&pv_hi, g_v_hi);
    cudaGetSymbolAddress(&pctx_hi, g_ctx_hi);
    cudaGetSymbolAddress(&pwt_hi, g_wt_hi);
    __half* hs_hi = (__half*)phs_hi;
    __half* wt_hi = (__half*)pwt_hi;

    mean_round_kernel<<<B_, H_>>>(hs, hs_hi);
    route_kernel<<<1, 256>>>(Wsc, bsc, Wsu, bsu);
    prep_w4_kernel<<<dim3(H_ / 32, H_ / 32, 32), dim3(32, 8)>>>(Wq, Wk, Wv, Wo, wt_hi);

    cudaFuncSetAttribute(gemm_qkv_kernel, cudaFuncAttributeMaxDynamicSharedMemorySize, GEMM_SMEM);
    cudaFuncSetAttribute(gemm_o_kernel,   cudaFuncAttributeMaxDynamicSharedMemorySize, GEMM_SMEM);

    // fused Q/K/V projections (Q epilogue scale = 0.125*log2e)
    gemm_qkv_kernel<<<dim3(18, S_ / 256, B_), 256, GEMM_SMEM>>>(
        hs_hi, wt_hi, bq, bk, bv,
        (__half*)pq_hi, (__half*)pk_hi, (__half*)pv_hi);

    cudaFuncSetAttribute(attn_mma_kernel, cudaFuncAttributeMaxDynamicSharedMemorySize, ATTN_SMEM);
    attn_mma_kernel<<<dim3(S_ / 128, NH_, B_), 256, ATTN_SMEM>>>(mask,
        (const __half*)pq_hi, (const __half*)pk_hi, (const __half*)pv_hi,
        (__half*)pctx_hi);

    // O projection: 1-term, f32 output
    gemm_o_kernel<<<dim3(H_ / 128, S_ / 256, B_), 256, GEMM_SMEM>>>(
        (const __half*)pctx_hi, wt_hi + 3 * WT_PER, bo, out);
}

// round 15
// speedup vs baseline: 1.0483x; 1.0483x over previous
#include <cuda_runtime.h>
#include <cuda_fp16.h>
#include <cstdint>

// ---------------- problem constants ----------------
#define B_  32
#define S_  512
#define H_  768
#define NH_ 12
#define DH_ 64
#define EC_ 4
#define EU_ 4
#define CAP_ 8   // int(1.0 * 32 / 4)

#define NELEM (B_ * S_ * H_)
#define LOG2E_ 1.4426950408889634f
#define QSCALE_ (0.125f * LOG2E_)

// ---------------- scratch (static device memory; no allocs) ----------------
__device__ float g_hmean[B_ * H_];
__device__ int   g_eidx[B_];
__device__ int   g_used[8];
__device__ __align__(16) __half g_hs_hi[NELEM];
__device__ __align__(16) __half g_q_hi[NELEM];
__device__ __align__(16) __half g_k_hi[NELEM];
__device__ __align__(16) __half g_v_hi[NELEM];
__device__ __align__(16) __half g_ctx_hi[NELEM];
// transposed expert weights (hi only): [mat(4)][e(8)][n(768)][k(768)]
#define WT_PER (8 * H_ * H_)
__device__ __align__(16) __half g_wt_hi[4 * WT_PER];

// ================= PTX helpers (baseline PTX only) =================
__device__ __forceinline__ uint32_t smem_u32(const void* p) {
    uint32_t a;
    asm("{ .reg .u64 t; cvta.to.shared.u64 t, %1; cvt.u32.u64 %0, t; }" : "=r"(a) : "l"(p));
    return a;
}

__device__ __forceinline__ void cp16(uint32_t saddr, const void* gaddr) {
    asm volatile("cp.async.cg.shared.global [%0], [%1], 16;" :: "r"(saddr), "l"(gaddr));
}
#define CP_COMMIT() asm volatile("cp.async.commit_group;" ::: "memory")
#define CP_WAIT1()  asm volatile("cp.async.wait_group 1;" ::: "memory")
#define CP_WAIT0()  asm volatile("cp.async.wait_group 0;" ::: "memory")

#define LDSM_X4(r, addr) \
    asm volatile("ldmatrix.sync.aligned.m8n8.x4.shared.b16 {%0,%1,%2,%3}, [%4];" \
        : "=r"((r)[0]), "=r"((r)[1]), "=r"((r)[2]), "=r"((r)[3]) : "r"(addr))

#define LDSM_X4_T(r, addr) \
    asm volatile("ldmatrix.sync.aligned.m8n8.x4.trans.shared.b16 {%0,%1,%2,%3}, [%4];" \
        : "=r"((r)[0]), "=r"((r)[1]), "=r"((r)[2]), "=r"((r)[3]) : "r"(addr))

#define MMA_F16(c, a, bb) \
    asm volatile("mma.sync.aligned.m16n8k16.row.col.f32.f16.f16.f32 " \
        "{%0,%1,%2,%3}, {%4,%5,%6,%7}, {%8,%9}, {%0,%1,%2,%3};" \
        : "+f"((c)[0]), "+f"((c)[1]), "+f"((c)[2]), "+f"((c)[3]) \
        : "r"((a)[0]), "r"((a)[1]), "r"((a)[2]), "r"((a)[3]), "r"((bb)[0]), "r"((bb)[1]))

__device__ __forceinline__ uint32_t packh(float lo, float hi) {
    uint32_t r;
    asm("cvt.rn.f16x2.f32 %0, %1, %2;" : "=r"(r) : "f"(hi), "f"(lo));
    return r;
}
__device__ __forceinline__ float ex2f(float x) {
    float y;
    asm("ex2.approx.ftz.f32 %0, %1;" : "=f"(y) : "f"(x));
    return y;
}

// ---------------- 1) mean over sequence + fp16 rounding of hs (fused) ----------------
__global__ void mean_round_kernel(const float* __restrict__ hs, __half* __restrict__ hi) {
    const int b = blockIdx.x;
    const int h = threadIdx.x;                 // 768 threads
    const float* p = hs + (size_t)b * S_ * H_ + h;
    __half* q = hi + (size_t)b * S_ * H_ + h;
    float acc = 0.f;
    #pragma unroll 8
    for (int s = 0; s < S_; s++) {
        const float x = p[(size_t)s * H_];
        acc += x;
        q[(size_t)s * H_] = __float2half_rn(x);
    }
    g_hmean[b * H_ + h] = acc * (1.0f / S_);
}

// ---------------- 2) routing + capacity drop (256 threads: 8 per sequence) ----------------
__global__ void route_kernel(const float* __restrict__ Wsc, const float* __restrict__ bsc,
                             const float* __restrict__ Wsu, const float* __restrict__ bsu) {
    __shared__ float pcmax[B_];
    __shared__ int   rcs[B_];
    __shared__ int   rus[B_];
    const int tid = threadIdx.x;
    const int g = tid & 7;
    const int b = tid >> 3;
    if (tid < 8) g_used[tid] = 0;
    {
        float lc[EC_] = {}, lu[EU_] = {};
        for (int h = g; h < H_; h += 8) {
            float x = g_hmean[b * H_ + h];
            #pragma unroll
            for (int e = 0; e < EC_; e++) lc[e] += x * Wsc[h * EC_ + e];
            #pragma unroll
            for (int e = 0; e < EU_; e++) lu[e] += x * Wsu[h * EU_ + e];
        }
        #pragma unroll
        for (int m = 1; m < 8; m <<= 1) {
            #pragma unroll
            for (int e = 0; e < EC_; e++) lc[e] += __shfl_xor_sync(0xffffffffu, lc[e], m);
            #pragma unroll
            for (int e = 0; e < EU_; e++) lu[e] += __shfl_xor_sync(0xffffffffu, lu[e], m);
        }
        if (g == 0) {
            #pragma unroll
            for (int e = 0; e < EC_; e++) lc[e] += bsc[e];
            #pragma unroll
            for (int e = 0; e < EU_; e++) lu[e] += bsu[e];
            float mc = lc[0]; int rc = 0;
            #pragma unroll
            for (int e = 1; e < EC_; e++) if (lc[e] > mc) { mc = lc[e]; rc = e; }
            float sc = 0.f;
            #pragma unroll
            for (int e = 0; e < EC_; e++) sc += __expf(lc[e] - mc);
            float mu = lu[0]; int ru = 0;
            #pragma unroll
            for (int e = 1; e < EU_; e++) if (lu[e] > mu) { mu = lu[e]; ru = e; }
            pcmax[b] = 1.f / sc;
            rcs[b] = rc;
            rus[b] = ru;
        }
    }
    __syncthreads();
    if (tid < B_) {
        const int b2i = tid;
        int rank = 1;
        const float pm = pcmax[b2i];
        const int   rc = rcs[b2i];
        for (int b2 = 0; b2 < B_; b2++) {
            if (b2 == b2i || rcs[b2] != rc) continue;
            if (pcmax[b2] > pm || (pcmax[b2] == pm && b2 < b2i)) rank++;
        }
        const int ei = (rank <= CAP_) ? rc : (EC_ + rus[b2i]);
        g_eidx[b2i] = ei;
        atomicExch(&g_used[ei], 1);
    }
}

// ---------------- prep: transpose used-expert W mats [e][k][n] -> Wt [mat][e][n][k], fp16 --------
__global__ void prep_w4_kernel(const float* __restrict__ W0, const float* __restrict__ W1,
                               const float* __restrict__ W2, const float* __restrict__ W3,
                               __half* __restrict__ th) {
    __shared__ float tile[32][33];
    const int mz = blockIdx.z;
    const int mat = mz >> 3, e = mz & 7;
    if (!g_used[e]) return;
    const int n0 = blockIdx.x * 32;
    const int k0 = blockIdx.y * 32;
    const int tx = threadIdx.x, ty = threadIdx.y;   // 32 x 8
    const float* W = (mat == 0 ? W0 : mat == 1 ? W1 : mat == 2 ? W2 : W3);
    const float* We = W + (size_t)e * H_ * H_;
    __half* to = th + (size_t)mat * WT_PER + (size_t)e * H_ * H_;
    #pragma unroll
    for (int j = 0; j < 32; j += 8)
        tile[ty + j][tx] = We[(size_t)(k0 + ty + j) * H_ + n0 + tx];
    __syncthreads();
    #pragma unroll
    for (int j = 0; j < 32; j += 8) {
        float x = tile[tx][ty + j];
        to[(size_t)(n0 + ty + j) * H_ + k0 + tx] = __float2half_rn(x);
    }
}

// ================ core GEMM tile routine (1-term fp16, 3-stage BK=64, CTA 128x128) ================
// (R12/R13 proven geometry) 8 warps as 2(M) x 4(N); warp tile 64x32.
#define GST    36864
#define GB_OFF 18432
#define KIT    (H_ / 64)        // 12
#define GEMM_SMEM (3 * GST)     // 110592

struct GemmAcc { float a[4][4][4]; };   // [mt(4 x 16rows)][nt(4 x 8cols)][frag]

__device__ __forceinline__ void gemm_tile_body(
    uint32_t sbase, const __half* Ah, const __half* Wh, int tid, GemmAcc& G) {
    const int lane = tid & 31, wid = tid >> 5;
    const int warp_m = (wid & 1) * 64, warp_n = (wid >> 1) * 32;

    auto issue = [&](int kc) {
        const uint32_t sb = sbase + (uint32_t)(kc % 3) * GST;
        const int k0 = kc * 64;
        #pragma unroll
        for (int i = 0; i < 4; i++) {
            const int idx = i * 256 + tid;
            const int row = idx >> 3, c = idx & 7;
            cp16(sb + row * 144 + c * 16, Ah + (size_t)row * H_ + k0 + c * 8);
        }
        #pragma unroll
        for (int i = 0; i < 4; i++) {
            const int idx = i * 256 + tid;
            const int row = idx >> 3, c = idx & 7;
            cp16(sb + GB_OFF + row * 144 + c * 16, Wh + (size_t)row * H_ + k0 + c * 8);
        }
        CP_COMMIT();
    };

    issue(0);
    issue(1);
    for (int kc = 0; kc < KIT; kc++) {
        if (kc < KIT - 1) { CP_WAIT1(); } else { CP_WAIT0(); }
        __syncthreads();
        if (kc + 2 < KIT) issue(kc + 2);
        const uint32_t sb = sbase + (uint32_t)(kc % 3) * GST;
        #pragma unroll
        for (int ks = 0; ks < 64; ks += 16) {
            uint32_t bh[2][4], ah[4][4];
            #pragma unroll
            for (int p = 0; p < 2; p++) {
                const uint32_t addr = sb + GB_OFF +
                    (uint32_t)((warp_n + p * 16 + (lane >> 4) * 8 + (lane & 7)) * 144 +
                               (ks + ((lane >> 3) & 1) * 8) * 2);
                LDSM_X4(bh[p], addr);
            }
            #pragma unroll
            for (int mt = 0; mt < 4; mt++) {
                const uint32_t addr = sb +
                    (uint32_t)((warp_m + mt * 16 + (lane & 15)) * 144 +
                               (ks + (lane >> 4) * 8) * 2);
                LDSM_X4(ah[mt], addr);
            }
            #pragma unroll
            for (int mt = 0; mt < 4; mt++) {
                #pragma unroll
                for (int nt = 0; nt < 4; nt++) {
                    uint32_t* bhp = &bh[nt >> 1][(nt & 1) * 2];
                    MMA_F16(G.a[mt][nt], ah[mt], bhp);
                }
            }
        }
    }
}

// ---------------- fused QKV projection: 3 mats in one launch ----------------
// grid (18, 4, 32): mat = bx/6, n0 = (bx%6)*128
__global__ __launch_bounds__(256, 2) void gemm_qkv_kernel(
    const __half* __restrict__ a_hi, const __half* __restrict__ w_all,
    const float* __restrict__ bq, const float* __restrict__ bk, const float* __restrict__ bv,
    __half* __restrict__ qout, __half* __restrict__ kout, __half* __restrict__ vout) {
    extern __shared__ char smem[];
    const uint32_t sbase = smem_u32(smem);
    const int tid = threadIdx.x;
    const int lane = tid & 31, wid = tid >> 5;
    const int mat = blockIdx.x / 6;
    const int n0  = (blockIdx.x % 6) * 128;
    const int b  = blockIdx.z;
    const int e  = g_eidx[b];
    const int bm = blockIdx.y * 128;
    const int warp_m = (wid & 1) * 64, warp_n = (wid >> 1) * 32;

    const float* bias = (mat == 0) ? bq : (mat == 1) ? bk : bv;
    __half* outp      = (mat == 0) ? qout : (mat == 1) ? kout : vout;
    const float scale = (mat == 0) ? QSCALE_ : 1.0f;

    const __half* Ah = a_hi + ((size_t)b * S_ + bm) * H_;
    const __half* Wh = w_all + (size_t)mat * WT_PER + ((size_t)e * H_ + n0) * H_;

    GemmAcc G = {};
    gemm_tile_body(sbase, Ah, Wh, tid, G);

    const int col_c = n0 + warp_n + (lane & 3) * 2;
    #pragma unroll
    for (int mt = 0; mt < 4; mt++) {
        const int r0 = bm + warp_m + mt * 16 + (lane >> 2);
        #pragma unroll
        for (int nt = 0; nt < 4; nt++) {
            const int cc = col_c + nt * 8;
            const float b0 = bias[e * H_ + cc];
            const float b1 = bias[e * H_ + cc + 1];
            float v00 = (G.a[mt][nt][0] + b0) * scale, v01 = (G.a[mt][nt][1] + b1) * scale;
            float v10 = (G.a[mt][nt][2] + b0) * scale, v11 = (G.a[mt][nt][3] + b1) * scale;
            const size_t o0 = ((size_t)b * S_ + r0) * H_ + cc;
            const size_t o1 = ((size_t)b * S_ + r0 + 8) * H_ + cc;
            *(uint32_t*)(outp + o0) = packh(v00, v01);
            *(uint32_t*)(outp + o1) = packh(v10, v11);
        }
    }
}

// ---------------- O projection (1-term, f32 out) ----------------
__global__ __launch_bounds__(256, 2) void gemm_o_kernel(
    const __half* __restrict__ a_hi, const __half* __restrict__ w_hi,
    const float* __restrict__ bias, float* __restrict__ C) {
    extern __shared__ char smem[];
    const uint32_t sbase = smem_u32(smem);
    const int tid = threadIdx.x;
    const int lane = tid & 31, wid = tid >> 5;
    const int b  = blockIdx.z;
    const int e  = g_eidx[b];
    const int n0 = blockIdx.x * 128;
    const int bm = blockIdx.y * 128;
    const int warp_m = (wid & 1) * 64, warp_n = (wid >> 1) * 32;

    const __half* Ah = a_hi + ((size_t)b * S_ + bm) * H_;
    const __half* Wh = w_hi + ((size_t)e * H_ + n0) * H_;

    GemmAcc G = {};
    gemm_tile_body(sbase, Ah, Wh, tid, G);

    float* Cb = C + (size_t)b * S_ * H_;
    const int col_c = n0 + warp_n + (lane & 3) * 2;
    #pragma unroll
    for (int mt = 0; mt < 4; mt++) {
        const int r0 = bm + warp_m + mt * 16 + (lane >> 2);
        #pragma unroll
        for (int nt = 0; nt < 4; nt++) {
            const int cc = col_c + nt * 8;
            const float b0 = bias[e * H_ + cc];
            const float b1 = bias[e * H_ + cc + 1];
            *(float2*)(Cb + (size_t)r0 * H_ + cc) =
                make_float2(G.a[mt][nt][0] + b0, G.a[mt][nt][1] + b1);
            *(float2*)(Cb + (size_t)(r0 + 8) * H_ + cc) =
                make_float2(G.a[mt][nt][2] + b0, G.a[mt][nt][3] + b1);
        }
    }
}

// ---------------- flash attention via mma.sync (np-pipelined QK->softmax->PV) ----------------
// Q pre-scaled by 0.125*log2e. Mask pre-scaled by log2e in smem. p = 2^(c + mask').
// Software pipeline: QK MMAs for np+1 issued BEFORE softmax/PV of np, so the tensor
// pipe has independent work while the ex2 chain resolves.
#define AT_STR 144                   // bytes per smem row
#define AT_TILE (128 * AT_STR)       // 18432 B
#define AT_QH 0
#define AT_KV AT_TILE                // per-buf: Kh, Vh
#define AT_BUF (2 * AT_TILE)
#define AT_MASK (AT_KV + 2 * AT_BUF) // 92160
#define ATTN_SMEM (AT_MASK + 2048)   // 94208

__global__ __launch_bounds__(256, 2) void attn_mma_kernel(
    const float* __restrict__ mask,
    const __half* __restrict__ qh_g,
    const __half* __restrict__ kh_g, const __half* __restrict__ vh_g,
    __half* __restrict__ ctx_hi) {
    extern __shared__ char smc[];
    const uint32_t sb = smem_u32(smc);
    const int tid = threadIdx.x;
    const int lane = tid & 31, w = tid >> 5;
    const int q0 = blockIdx.x * 128;
    const int hh = blockIdx.y;
    const int b  = blockIdx.z;
    const int r8 = lane & 7, g = lane >> 3;
    const float* mask_s = (const float*)(smc + AT_MASK);

    auto load_q = [&]() {
        #pragma unroll
        for (int i = 0; i < 4; i++) {
            const int idx = i * 256 + tid;
            const int row = idx >> 3, c16 = (idx & 7) * 16, ce = (idx & 7) * 8;
            const size_t ga = ((size_t)b * S_ + q0 + row) * H_ + hh * DH_ + ce;
            cp16(sb + AT_QH + row * AT_STR + c16, qh_g + ga);
        }
    };
    auto load_kv = [&](int t) {
        const uint32_t kb = sb + AT_KV + (t & 1) * AT_BUF;
        #pragma unroll
        for (int i = 0; i < 4; i++) {
            const int idx = i * 256 + tid;
            const int row = idx >> 3, c16 = (idx & 7) * 16, ce = (idx & 7) * 8;
            const size_t ga = ((size_t)b * S_ + t * 128 + row) * H_ + hh * DH_ + ce;
            const uint32_t so = row * AT_STR + c16;
            cp16(kb + so,           kh_g + ga);
            cp16(kb + AT_TILE + so, vh_g + ga);
        }
    };

    load_q(); load_kv(0); CP_COMMIT();
    load_kv(1); CP_COMMIT();
    if (tid < 128) {
        float4 m = *(const float4*)(mask + (size_t)b * S_ + tid * 4);
        *(float4*)(smc + AT_MASK + tid * 16) =
            make_float4(m.x * LOG2E_, m.y * LOG2E_, m.z * LOG2E_, m.w * LOG2E_);
    }

    uint32_t qh[4][4];
    float o[8][4] = {};
    float l1 = 0.f, l2 = 0.f;

    for (int t = 0; t < 4; t++) {
        if (t < 3) { CP_WAIT1(); } else { CP_WAIT0(); }
        __syncthreads();

        if (t == 0) {
            #pragma unroll
            for (int kc = 0; kc < 4; kc++) {
                const uint32_t qa = sb + (uint32_t)((w * 16 + (g & 1) * 8 + r8) * AT_STR +
                                                    (kc * 16 + (g >> 1) * 8) * 2);
                LDSM_X4(qh[kc], qa + AT_QH);
            }
        }

        const uint32_t kb = sb + AT_KV + (t & 1) * AT_BUF;

        // QK score computation for one key-chunk np
        auto qk = [&](int np, float* cc0, float* cc1) {
            #pragma unroll
            for (int x = 0; x < 4; x++) { cc0[x] = 0.f; cc1[x] = 0.f; }
            #pragma unroll
            for (int kc = 0; kc < 4; kc++) {
                uint32_t bh[4];
                const uint32_t ka = kb + (uint32_t)((np * 16 + (g >> 1) * 8 + r8) * AT_STR +
                                                    (kc * 16 + (g & 1) * 8) * 2);
                LDSM_X4(bh, ka);
                MMA_F16(cc0, qh[kc], bh);
                MMA_F16(cc1, qh[kc], bh + 2);
            }
        };

        float c0[4], c1[4];
        qk(0, c0, c1);                         // prologue
        #pragma unroll
        for (int np = 0; np < 8; np++) {
            float n0r[4], n1r[4];
            if (np < 7) qk(np + 1, n0r, n1r);  // next chunk's QK (independent of cur softmax)
            // V fragments for current chunk (independent of softmax)
            uint32_t vf[4][4];
            #pragma unroll
            for (int nv = 0; nv < 4; nv++) {
                const uint32_t va = kb + AT_TILE +
                    (uint32_t)((np * 16 + (g & 1) * 8 + r8) * AT_STR +
                               (nv * 16 + (g >> 1) * 8) * 2);
                LDSM_X4_T(vf[nv], va);
            }
            // softmax numerator for current chunk
            const int key0 = t * 128 + np * 16 + 2 * (lane & 3);
            const float mk00 = mask_s[key0],     mk01 = mask_s[key0 + 1];
            const float mk10 = mask_s[key0 + 8], mk11 = mask_s[key0 + 9];
            c0[0] = ex2f(c0[0] + mk00); c0[1] = ex2f(c0[1] + mk01);
            c0[2] = ex2f(c0[2] + mk00); c0[3] = ex2f(c0[3] + mk01);
            c1[0] = ex2f(c1[0] + mk10); c1[1] = ex2f(c1[1] + mk11);
            c1[2] = ex2f(c1[2] + mk10); c1[3] = ex2f(c1[3] + mk11);
            l1 += c0[0] + c0[1] + c1[0] + c1[1];
            l2 += c0[2] + c0[3] + c1[2] + c1[3];
            uint32_t ph[4];
            ph[0] = packh(c0[0], c0[1]);
            ph[1] = packh(c0[2], c0[3]);
            ph[2] = packh(c1[0], c1[1]);
            ph[3] = packh(c1[2], c1[3]);
            #pragma unroll
            for (int nv = 0; nv < 4; nv++) {
                MMA_F16(o[2*nv],   ph, vf[nv]);
                MMA_F16(o[2*nv+1], ph, vf[nv] + 2);
            }
            if (np < 7) {
                #pragma unroll
                for (int x = 0; x < 4; x++) { c0[x] = n0r[x]; c1[x] = n1r[x]; }
            }
        }
        __syncthreads();
        if (t < 2) { load_kv(t + 2); CP_COMMIT(); }
    }

    // ---- epilogue ----
    l1 += __shfl_xor_sync(0xffffffffu, l1, 1);
    l1 += __shfl_xor_sync(0xffffffffu, l1, 2);
    l2 += __shfl_xor_sync(0xffffffffu, l2, 1);
    l2 += __shfl_xor_sync(0xffffffffu, l2, 2);
    const float inv1 = 1.f / l1, inv2 = 1.f / l2;
    const int row1 = q0 + w * 16 + (lane >> 2);
    #pragma unroll
    for (int nt = 0; nt < 8; nt++) {
        const int dh = hh * DH_ + nt * 8 + 2 * (lane & 3);
        const size_t o0 = ((size_t)b * S_ + row1) * H_ + dh;
        const size_t o1 = ((size_t)b * S_ + row1 + 8) * H_ + dh;
        *(uint32_t*)(ctx_hi + o0) = packh(o[nt][0] * inv1, o[nt][1] * inv1);
        *(uint32_t*)(ctx_hi + o1) = packh(o[nt][2] * inv2, o[nt][3] * inv2);
    }
}

// ---------------- launch ----------------
extern "C" void kernel_launch(void* const* d_in, const int* in_sizes, int n_in,
                              void* d_out, int out_size) {
    const float* hs   = (const float*)d_in[0];
    const float* mask = (const float*)d_in[1];
    const float* Wq = (const float*)d_in[2];
    const float* bq = (const float*)d_in[3];
    const float* Wk = (const float*)d_in[4];
    const float* bk = (const float*)d_in[5];
    const float* Wv = (const float*)d_in[6];
    const float* bv = (const float*)d_in[7];
    const float* Wo = (const float*)d_in[8];
    const float* bo = (const float*)d_in[9];
    const float* Wsc = (const float*)d_in[10];
    const float* bsc = (const float*)d_in[11];
    const float* Wsu = (const float*)d_in[12];
    const float* bsu = (const float*)d_in[13];
    float* out = (float*)d_out;

    void *phs_hi, *pq_hi, *pk_hi, *pv_hi, *pctx_hi, *pwt_hi;
    cudaGetSymbolAddress(&phs_hi, g_hs_hi);
    cudaGetSymbolAddress(&pq_hi, g_q_hi);
    cudaGetSymbolAddress(&pk_hi, g_k_hi);
    cudaGetSymbolAddress(&pv_hi, g_v_hi);
    cudaGetSymbolAddress(&pctx_hi, g_ctx_hi);
    cudaGetSymbolAddress(&pwt_hi, g_wt_hi);
    __half* hs_hi = (__half*)phs_hi;
    __half* wt_hi = (__half*)pwt_hi;

    mean_round_kernel<<<B_, H_>>>(hs, hs_hi);
    route_kernel<<<1, 256>>>(Wsc, bsc, Wsu, bsu);
    prep_w4_kernel<<<dim3(H_ / 32, H_ / 32, 32), dim3(32, 8)>>>(Wq, Wk, Wv, Wo, wt_hi);

    cudaFuncSetAttribute(gemm_qkv_kernel, cudaFuncAttributeMaxDynamicSharedMemorySize, GEMM_SMEM);
    cudaFuncSetAttribute(gemm_o_kernel,   cudaFuncAttributeMaxDynamicSharedMemorySize, GEMM_SMEM);

    // fused Q/K/V projections (Q epilogue scale = 0.125*log2e)
    gemm_qkv_kernel<<<dim3(18, S_ / 128, B_), 256, GEMM_SMEM>>>(
        hs_hi, wt_hi, bq, bk, bv,
        (__half*)pq_hi, (__half*)pk_hi, (__half*)pv_hi);

    cudaFuncSetAttribute(attn_mma_kernel, cudaFuncAttributeMaxDynamicSharedMemorySize, ATTN_SMEM);
    attn_mma_kernel<<<dim3(S_ / 128, NH_, B_), 256, ATTN_SMEM>>>(mask,
        (const __half*)pq_hi, (const __half*)pk_hi, (const __half*)pv_hi,
        (__half*)pctx_hi);

    // O projection: 1-term, f32 output
    gemm_o_kernel<<<dim3(H_ / 128, S_ / 128, B_), 256, GEMM_SMEM>>>(
        (const __half*)pctx_hi, wt_hi + 3 * WT_PER, bo, out);
}

// round 16
// speedup vs baseline: 1.0711x; 1.0218x over previous
#include <cuda_runtime.h>
#include <cuda_fp16.h>
#include <cstdint>

// ---------------- problem constants ----------------
#define B_  32
#define S_  512
#define H_  768
#define NH_ 12
#define DH_ 64
#define EC_ 4
#define EU_ 4
#define CAP_ 8   // int(1.0 * 32 / 4)

#define NELEM (B_ * S_ * H_)
#define LOG2E_ 1.4426950408889634f
#define QSCALE_ (0.125f * LOG2E_)

// ---------------- scratch (static device memory; no allocs) ----------------
__device__ float g_hmean[B_ * H_];
__device__ int   g_eidx[B_];
__device__ int   g_used[8];
__device__ __align__(16) __half g_hs_hi[NELEM];
__device__ __align__(16) __half g_q_hi[NELEM];
__device__ __align__(16) __half g_k_hi[NELEM];
__device__ __align__(16) __half g_v_hi[NELEM];
__device__ __align__(16) __half g_ctx_hi[NELEM];
// expert weights fp16, NATIVE [mat(4)][e(8)][k(768)][n(768)] layout (no transpose)
#define WT_PER (8 * H_ * H_)
__device__ __align__(16) __half g_wt_hi[4 * WT_PER];

// ================= PTX helpers (baseline PTX only) =================
__device__ __forceinline__ uint32_t smem_u32(const void* p) {
    uint32_t a;
    asm("{ .reg .u64 t; cvta.to.shared.u64 t, %1; cvt.u32.u64 %0, t; }" : "=r"(a) : "l"(p));
    return a;
}

__device__ __forceinline__ void cp16(uint32_t saddr, const void* gaddr) {
    asm volatile("cp.async.cg.shared.global [%0], [%1], 16;" :: "r"(saddr), "l"(gaddr));
}
#define CP_COMMIT() asm volatile("cp.async.commit_group;" ::: "memory")
#define CP_WAIT1()  asm volatile("cp.async.wait_group 1;" ::: "memory")
#define CP_WAIT0()  asm volatile("cp.async.wait_group 0;" ::: "memory")

#define LDSM_X4(r, addr) \
    asm volatile("ldmatrix.sync.aligned.m8n8.x4.shared.b16 {%0,%1,%2,%3}, [%4];" \
        : "=r"((r)[0]), "=r"((r)[1]), "=r"((r)[2]), "=r"((r)[3]) : "r"(addr))

#define LDSM_X4_T(r, addr) \
    asm volatile("ldmatrix.sync.aligned.m8n8.x4.trans.shared.b16 {%0,%1,%2,%3}, [%4];" \
        : "=r"((r)[0]), "=r"((r)[1]), "=r"((r)[2]), "=r"((r)[3]) : "r"(addr))

#define MMA_F16(c, a, bb) \
    asm volatile("mma.sync.aligned.m16n8k16.row.col.f32.f16.f16.f32 " \
        "{%0,%1,%2,%3}, {%4,%5,%6,%7}, {%8,%9}, {%0,%1,%2,%3};" \
        : "+f"((c)[0]), "+f"((c)[1]), "+f"((c)[2]), "+f"((c)[3]) \
        : "r"((a)[0]), "r"((a)[1]), "r"((a)[2]), "r"((a)[3]), "r"((bb)[0]), "r"((bb)[1]))

__device__ __forceinline__ uint32_t packh(float lo, float hi) {
    uint32_t r;
    asm("cvt.rn.f16x2.f32 %0, %1, %2;" : "=r"(r) : "f"(hi), "f"(lo));
    return r;
}
__device__ __forceinline__ float ex2f(float x) {
    float y;
    asm("ex2.approx.ftz.f32 %0, %1;" : "=f"(y) : "f"(x));
    return y;
}

// ---------------- 1) mean over sequence + fp16 rounding of hs (fused) ----------------
__global__ void mean_round_kernel(const float* __restrict__ hs, __half* __restrict__ hi) {
    const int b = blockIdx.x;
    const int h = threadIdx.x;                 // 768 threads
    const float* p = hs + (size_t)b * S_ * H_ + h;
    __half* q = hi + (size_t)b * S_ * H_ + h;
    float acc = 0.f;
    #pragma unroll 8
    for (int s = 0; s < S_; s++) {
        const float x = p[(size_t)s * H_];
        acc += x;
        q[(size_t)s * H_] = __float2half_rn(x);
    }
    g_hmean[b * H_ + h] = acc * (1.0f / S_);
}

// ---------------- 2) routing + capacity drop (256 threads: 8 per sequence) ----------------
__global__ void route_kernel(const float* __restrict__ Wsc, const float* __restrict__ bsc,
                             const float* __restrict__ Wsu, const float* __restrict__ bsu) {
    __shared__ float pcmax[B_];
    __shared__ int   rcs[B_];
    __shared__ int   rus[B_];
    const int tid = threadIdx.x;
    const int g = tid & 7;
    const int b = tid >> 3;
    if (tid < 8) g_used[tid] = 0;
    {
        float lc[EC_] = {}, lu[EU_] = {};
        for (int h = g; h < H_; h += 8) {
            float x = g_hmean[b * H_ + h];
            #pragma unroll
            for (int e = 0; e < EC_; e++) lc[e] += x * Wsc[h * EC_ + e];
            #pragma unroll
            for (int e = 0; e < EU_; e++) lu[e] += x * Wsu[h * EU_ + e];
        }
        #pragma unroll
        for (int m = 1; m < 8; m <<= 1) {
            #pragma unroll
            for (int e = 0; e < EC_; e++) lc[e] += __shfl_xor_sync(0xffffffffu, lc[e], m);
            #pragma unroll
            for (int e = 0; e < EU_; e++) lu[e] += __shfl_xor_sync(0xffffffffu, lu[e], m);
        }
        if (g == 0) {
            #pragma unroll
            for (int e = 0; e < EC_; e++) lc[e] += bsc[e];
            #pragma unroll
            for (int e = 0; e < EU_; e++) lu[e] += bsu[e];
            float mc = lc[0]; int rc = 0;
            #pragma unroll
            for (int e = 1; e < EC_; e++) if (lc[e] > mc) { mc = lc[e]; rc = e; }
            float sc = 0.f;
            #pragma unroll
            for (int e = 0; e < EC_; e++) sc += __expf(lc[e] - mc);
            float mu = lu[0]; int ru = 0;
            #pragma unroll
            for (int e = 1; e < EU_; e++) if (lu[e] > mu) { mu = lu[e]; ru = e; }
            pcmax[b] = 1.f / sc;
            rcs[b] = rc;
            rus[b] = ru;
        }
    }
    __syncthreads();
    if (tid < B_) {
        const int b2i = tid;
        int rank = 1;
        const float pm = pcmax[b2i];
        const int   rc = rcs[b2i];
        for (int b2 = 0; b2 < B_; b2++) {
            if (b2 == b2i || rcs[b2] != rc) continue;
            if (pcmax[b2] > pm || (pcmax[b2] == pm && b2 < b2i)) rank++;
        }
        const int ei = (rank <= CAP_) ? rc : (EC_ + rus[b2i]);
        g_eidx[b2i] = ei;
        atomicExch(&g_used[ei], 1);
    }
}

// ---------------- prep: pure f32->fp16 convert of used-expert W mats (native layout) ----------
// grid (144, 1, 32): mz -> (mat, e); each block converts 4096 floats x ... actually
// block covers H*H/144 segment: use 2D: blockIdx.x = segment (0..143), 256 threads x 4 f4 each.
__global__ __launch_bounds__(256) void conv_w4_kernel(
    const float* __restrict__ W0, const float* __restrict__ W1,
    const float* __restrict__ W2, const float* __restrict__ W3,
    __half* __restrict__ th) {
    const int mz = blockIdx.z;                 // 0..31: mat*8 + e
    const int mat = mz >> 3, e = mz & 7;
    if (!g_used[e]) return;
    const float* W = (mat == 0 ? W0 : mat == 1 ? W1 : mat == 2 ? W2 : W3);
    const float4* src = (const float4*)(W + (size_t)e * H_ * H_);
    uint2* dst = (uint2*)(th + (size_t)mat * WT_PER + (size_t)e * H_ * H_);
    // H*H/4 = 147456 float4; 576 blocks of 256 threads -> 1 f4 each
    const int i = blockIdx.x * 256 + threadIdx.x;
    float4 x = src[i];
    uint2 h;
    h.x = packh(x.x, x.y); h.y = packh(x.z, x.w);
    dst[i] = h;
}

// ================ core GEMM tile routine (1-term fp16, 3-stage BK=64, CTA 128x128) ================
// 8 warps as 2(M) x 4(N); warp tile 64x32. A tile [128 m][64 k] rows 144B;
// B tile k-major [64 k][128 n] rows 272B (256B data + 16B pad), consumed via LDSM.trans.
#define GA_SZ  18432                 // 128 * 144
#define GB_SZ  17408                 // 64 * 272
#define GST    (GA_SZ + GB_SZ)       // 35840
#define GB_OFF GA_SZ
#define KIT    (H_ / 64)             // 12
#define GEMM_SMEM (3 * GST)          // 107520

struct GemmAcc { float a[4][4][4]; };   // [mt(4 x 16rows)][nt(4 x 8cols)][frag]

__device__ __forceinline__ void gemm_tile_body(
    uint32_t sbase, const __half* Ah, const __half* Wh, int tid, GemmAcc& G) {
    const int lane = tid & 31, wid = tid >> 5;
    const int warp_m = (wid & 1) * 64, warp_n = (wid >> 1) * 32;
    const int r8 = lane & 7, g = lane >> 3;

    // Wh points at (k=0, n0): element (k, n) at Wh[k * H_ + n] (n0 already folded in)
    auto issue = [&](int kc) {
        const uint32_t sb = sbase + (uint32_t)(kc % 3) * GST;
        const int k0 = kc * 64;
        #pragma unroll
        for (int i = 0; i < 4; i++) {
            const int idx = i * 256 + tid;
            const int row = idx >> 3, c = idx & 7;
            cp16(sb + row * 144 + c * 16, Ah + (size_t)row * H_ + k0 + c * 8);
        }
        #pragma unroll
        for (int i = 0; i < 4; i++) {
            const int idx = i * 256 + tid;
            const int row = idx >> 4, c = idx & 15;   // 64 k-rows x 16 chunks of 16B
            cp16(sb + GB_OFF + row * 272 + c * 16, Wh + (size_t)(k0 + row) * H_ + c * 8);
        }
        CP_COMMIT();
    };

    issue(0);
    issue(1);
    for (int kc = 0; kc < KIT; kc++) {
        if (kc < KIT - 1) { CP_WAIT1(); } else { CP_WAIT0(); }
        __syncthreads();
        if (kc + 2 < KIT) issue(kc + 2);
        const uint32_t sb = sbase + (uint32_t)(kc % 3) * GST;
        #pragma unroll
        for (int ks = 0; ks < 64; ks += 16) {
            uint32_t bh[2][4], ah[4][4];
            #pragma unroll
            for (int p = 0; p < 2; p++) {
                // k-major B, trans-LDSM (same pattern as attention V):
                // rows = k (ks + (g&1)*8 + r8), cols = n (warp_n + p*16 + (g>>1)*8)
                const uint32_t addr = sb + GB_OFF +
                    (uint32_t)((ks + (g & 1) * 8 + r8) * 272 +
                               (warp_n + p * 16 + (g >> 1) * 8) * 2);
                LDSM_X4_T(bh[p], addr);
            }
            #pragma unroll
            for (int mt = 0; mt < 4; mt++) {
                const uint32_t addr = sb +
                    (uint32_t)((warp_m + mt * 16 + (lane & 15)) * 144 +
                               (ks + (lane >> 4) * 8) * 2);
                LDSM_X4(ah[mt], addr);
            }
            #pragma unroll
            for (int mt = 0; mt < 4; mt++) {
                #pragma unroll
                for (int nt = 0; nt < 4; nt++) {
                    uint32_t* bhp = &bh[nt >> 1][(nt & 1) * 2];
                    MMA_F16(G.a[mt][nt], ah[mt], bhp);
                }
            }
        }
    }
}

// ---------------- fused QKV projection: 3 mats in one launch ----------------
// grid (18, 4, 32): mat = bx/6, n0 = (bx%6)*128
__global__ __launch_bounds__(256, 2) void gemm_qkv_kernel(
    const __half* __restrict__ a_hi, const __half* __restrict__ w_all,
    const float* __restrict__ bq, const float* __restrict__ bk, const float* __restrict__ bv,
    __half* __restrict__ qout, __half* __restrict__ kout, __half* __restrict__ vout) {
    extern __shared__ char smem[];
    const uint32_t sbase = smem_u32(smem);
    const int tid = threadIdx.x;
    const int lane = tid & 31, wid = tid >> 5;
    const int mat = blockIdx.x / 6;
    const int n0  = (blockIdx.x % 6) * 128;
    const int b  = blockIdx.z;
    const int e  = g_eidx[b];
    const int bm = blockIdx.y * 128;
    const int warp_m = (wid & 1) * 64, warp_n = (wid >> 1) * 32;

    const float* bias = (mat == 0) ? bq : (mat == 1) ? bk : bv;
    __half* outp      = (mat == 0) ? qout : (mat == 1) ? kout : vout;
    const float scale = (mat == 0) ? QSCALE_ : 1.0f;

    const __half* Ah = a_hi + ((size_t)b * S_ + bm) * H_;
    const __half* Wh = w_all + (size_t)mat * WT_PER + (size_t)e * H_ * H_ + n0;

    GemmAcc G = {};
    gemm_tile_body(sbase, Ah, Wh, tid, G);

    const int col_c = n0 + warp_n + (lane & 3) * 2;
    #pragma unroll
    for (int mt = 0; mt < 4; mt++) {
        const int r0 = bm + warp_m + mt * 16 + (lane >> 2);
        #pragma unroll
        for (int nt = 0; nt < 4; nt++) {
            const int cc = col_c + nt * 8;
            const float b0 = bias[e * H_ + cc];
            const float b1 = bias[e * H_ + cc + 1];
            float v00 = (G.a[mt][nt][0] + b0) * scale, v01 = (G.a[mt][nt][1] + b1) * scale;
            float v10 = (G.a[mt][nt][2] + b0) * scale, v11 = (G.a[mt][nt][3] + b1) * scale;
            const size_t o0 = ((size_t)b * S_ + r0) * H_ + cc;
            const size_t o1 = ((size_t)b * S_ + r0 + 8) * H_ + cc;
            *(uint32_t*)(outp + o0) = packh(v00, v01);
            *(uint32_t*)(outp + o1) = packh(v10, v11);
        }
    }
}

// ---------------- O projection (1-term, f32 out) ----------------
__global__ __launch_bounds__(256, 2) void gemm_o_kernel(
    const __half* __restrict__ a_hi, const __half* __restrict__ w_hi,
    const float* __restrict__ bias, float* __restrict__ C) {
    extern __shared__ char smem[];
    const uint32_t sbase = smem_u32(smem);
    const int tid = threadIdx.x;
    const int lane = tid & 31, wid = tid >> 5;
    const int b  = blockIdx.z;
    const int e  = g_eidx[b];
    const int n0 = blockIdx.x * 128;
    const int bm = blockIdx.y * 128;
    const int warp_m = (wid & 1) * 64, warp_n = (wid >> 1) * 32;

    const __half* Ah = a_hi + ((size_t)b * S_ + bm) * H_;
    const __half* Wh = w_hi + (size_t)e * H_ * H_ + n0;

    GemmAcc G = {};
    gemm_tile_body(sbase, Ah, Wh, tid, G);

    float* Cb = C + (size_t)b * S_ * H_;
    const int col_c = n0 + warp_n + (lane & 3) * 2;
    #pragma unroll
    for (int mt = 0; mt < 4; mt++) {
        const int r0 = bm + warp_m + mt * 16 + (lane >> 2);
        #pragma unroll
        for (int nt = 0; nt < 4; nt++) {
            const int cc = col_c + nt * 8;
            const float b0 = bias[e * H_ + cc];
            const float b1 = bias[e * H_ + cc + 1];
            *(float2*)(Cb + (size_t)r0 * H_ + cc) =
                make_float2(G.a[mt][nt][0] + b0, G.a[mt][nt][1] + b1);
            *(float2*)(Cb + (size_t)(r0 + 8) * H_ + cc) =
                make_float2(G.a[mt][nt][2] + b0, G.a[mt][nt][3] + b1);
        }
    }
}

// ---------------- flash attention via mma.sync (fused QK->softmax->PV per key-chunk) ----------------
// Q pre-scaled by 0.125*log2e. Mask pre-scaled by log2e in smem. p = 2^(c + mask').
#define AT_STR 144                   // bytes per smem row
#define AT_TILE (128 * AT_STR)       // 18432 B
#define AT_QH 0
#define AT_KV AT_TILE                // per-buf: Kh, Vh
#define AT_BUF (2 * AT_TILE)
#define AT_MASK (AT_KV + 2 * AT_BUF) // 92160
#define ATTN_SMEM (AT_MASK + 2048)   // 94208

__global__ __launch_bounds__(256, 2) void attn_mma_kernel(
    const float* __restrict__ mask,
    const __half* __restrict__ qh_g,
    const __half* __restrict__ kh_g, const __half* __restrict__ vh_g,
    __half* __restrict__ ctx_hi) {
    extern __shared__ char smc[];
    const uint32_t sb = smem_u32(smc);
    const int tid = threadIdx.x;
    const int lane = tid & 31, w = tid >> 5;
    const int q0 = blockIdx.x * 128;
    const int hh = blockIdx.y;
    const int b  = blockIdx.z;
    const int r8 = lane & 7, g = lane >> 3;
    const float* mask_s = (const float*)(smc + AT_MASK);

    auto load_q = [&]() {
        #pragma unroll
        for (int i = 0; i < 4; i++) {
            const int idx = i * 256 + tid;
            const int row = idx >> 3, c16 = (idx & 7) * 16, ce = (idx & 7) * 8;
            const size_t ga = ((size_t)b * S_ + q0 + row) * H_ + hh * DH_ + ce;
            cp16(sb + AT_QH + row * AT_STR + c16, qh_g + ga);
        }
    };
    auto load_kv = [&](int t) {
        const uint32_t kb = sb + AT_KV + (t & 1) * AT_BUF;
        #pragma unroll
        for (int i = 0; i < 4; i++) {
            const int idx = i * 256 + tid;
            const int row = idx >> 3, c16 = (idx & 7) * 16, ce = (idx & 7) * 8;
            const size_t ga = ((size_t)b * S_ + t * 128 + row) * H_ + hh * DH_ + ce;
            const uint32_t so = row * AT_STR + c16;
            cp16(kb + so,           kh_g + ga);
            cp16(kb + AT_TILE + so, vh_g + ga);
        }
    };

    load_q(); load_kv(0); CP_COMMIT();
    load_kv(1); CP_COMMIT();
    if (tid < 128) {
        float4 m = *(const float4*)(mask + (size_t)b * S_ + tid * 4);
        *(float4*)(smc + AT_MASK + tid * 16) =
            make_float4(m.x * LOG2E_, m.y * LOG2E_, m.z * LOG2E_, m.w * LOG2E_);
    }

    uint32_t qh[4][4];
    float o[8][4] = {};
    float l1 = 0.f, l2 = 0.f;

    for (int t = 0; t < 4; t++) {
        if (t < 3) { CP_WAIT1(); } else { CP_WAIT0(); }
        __syncthreads();

        if (t == 0) {
            #pragma unroll
            for (int kc = 0; kc < 4; kc++) {
                const uint32_t qa = sb + (uint32_t)((w * 16 + (g & 1) * 8 + r8) * AT_STR +
                                                    (kc * 16 + (g >> 1) * 8) * 2);
                LDSM_X4(qh[kc], qa + AT_QH);
            }
        }

        const uint32_t kb = sb + AT_KV + (t & 1) * AT_BUF;
        #pragma unroll
        for (int np = 0; np < 8; np++) {
            float c0[4] = {}, c1[4] = {};
            #pragma unroll
            for (int kc = 0; kc < 4; kc++) {
                uint32_t bh[4];
                const uint32_t ka = kb + (uint32_t)((np * 16 + (g >> 1) * 8 + r8) * AT_STR +
                                                    (kc * 16 + (g & 1) * 8) * 2);
                LDSM_X4(bh, ka);
                MMA_F16(c0, qh[kc], bh);
                MMA_F16(c1, qh[kc], bh + 2);
            }
            uint32_t vf[4][4];
            #pragma unroll
            for (int nv = 0; nv < 4; nv++) {
                const uint32_t va = kb + AT_TILE +
                    (uint32_t)((np * 16 + (g & 1) * 8 + r8) * AT_STR +
                               (nv * 16 + (g >> 1) * 8) * 2);
                LDSM_X4_T(vf[nv], va);
            }
            const int key0 = t * 128 + np * 16 + 2 * (lane & 3);
            const float mk00 = mask_s[key0],     mk01 = mask_s[key0 + 1];
            const float mk10 = mask_s[key0 + 8], mk11 = mask_s[key0 + 9];
            c0[0] = ex2f(c0[0] + mk00); c0[1] = ex2f(c0[1] + mk01);
            c0[2] = ex2f(c0[2] + mk00); c0[3] = ex2f(c0[3] + mk01);
            c1[0] = ex2f(c1[0] + mk10); c1[1] = ex2f(c1[1] + mk11);
            c1[2] = ex2f(c1[2] + mk10); c1[3] = ex2f(c1[3] + mk11);
            l1 += c0[0] + c0[1] + c1[0] + c1[1];
            l2 += c0[2] + c0[3] + c1[2] + c1[3];
            uint32_t ph[4];
            ph[0] = packh(c0[0], c0[1]);
            ph[1] = packh(c0[2], c0[3]);
            ph[2] = packh(c1[0], c1[1]);
            ph[3] = packh(c1[2], c1[3]);
            #pragma unroll
            for (int nv = 0; nv < 4; nv++) {
                MMA_F16(o[2*nv],   ph, vf[nv]);
                MMA_F16(o[2*nv+1], ph, vf[nv] + 2);
            }
        }
        __syncthreads();
        if (t < 2) { load_kv(t + 2); CP_COMMIT(); }
    }

    // ---- epilogue ----
    l1 += __shfl_xor_sync(0xffffffffu, l1, 1);
    l1 += __shfl_xor_sync(0xffffffffu, l1, 2);
    l2 += __shfl_xor_sync(0xffffffffu, l2, 1);
    l2 += __shfl_xor_sync(0xffffffffu, l2, 2);
    const float inv1 = 1.f / l1, inv2 = 1.f / l2;
    const int row1 = q0 + w * 16 + (lane >> 2);
    #pragma unroll
    for (int nt = 0; nt < 8; nt++) {
        const int dh = hh * DH_ + nt * 8 + 2 * (lane & 3);
        const size_t o0 = ((size_t)b * S_ + row1) * H_ + dh;
        const size_t o1 = ((size_t)b * S_ + row1 + 8) * H_ + dh;
        *(uint32_t*)(ctx_hi + o0) = packh(o[nt][0] * inv1, o[nt][1] * inv1);
        *(uint32_t*)(ctx_hi + o1) = packh(o[nt][2] * inv2, o[nt][3] * inv2);
    }
}

// ---------------- launch ----------------
extern "C" void kernel_launch(void* const* d_in, const int* in_sizes, int n_in,
                              void* d_out, int out_size) {
    const float* hs   = (const float*)d_in[0];
    const float* mask = (const float*)d_in[1];
    const float* Wq = (const float*)d_in[2];
    const float* bq = (const float*)d_in[3];
    const float* Wk = (const float*)d_in[4];
    const float* bk = (const float*)d_in[5];
    const float* Wv = (const float*)d_in[6];
    const float* bv = (const float*)d_in[7];
    const float* Wo = (const float*)d_in[8];
    const float* bo = (const float*)d_in[9];
    const float* Wsc = (const float*)d_in[10];
    const float* bsc = (const float*)d_in[11];
    const float* Wsu = (const float*)d_in[12];
    const float* bsu = (const float*)d_in[13];
    float* out = (float*)d_out;

    void *phs_hi, *pq_hi, *pk_hi, *pv_hi, *pctx_hi, *pwt_hi;
    cudaGetSymbolAddress(&phs_hi, g_hs_hi);
    cudaGetSymbolAddress(&pq_hi, g_q_hi);
    cudaGetSymbolAddress(&pk_hi, g_k_hi);
    cudaGetSymbolAddress(&pv_hi, g_v_hi);
    cudaGetSymbolAddress(&pctx_hi, g_ctx_hi);
    cudaGetSymbolAddress(&pwt_hi, g_wt_hi);
    __half* hs_hi = (__half*)phs_hi;
    __half* wt_hi = (__half*)pwt_hi;

    mean_round_kernel<<<B_, H_>>>(hs, hs_hi);
    route_kernel<<<1, 256>>>(Wsc, bsc, Wsu, bsu);
    // pure convert (no transpose): 576 blocks cover H*H/4 float4 per (mat,e)
    conv_w4_kernel<<<dim3(H_ * H_ / 4 / 256, 1, 32), 256>>>(Wq, Wk, Wv, Wo, wt_hi);

    cudaFuncSetAttribute(gemm_qkv_kernel, cudaFuncAttributeMaxDynamicSharedMemorySize, GEMM_SMEM);
    cudaFuncSetAttribute(gemm_o_kernel,   cudaFuncAttributeMaxDynamicSharedMemorySize, GEMM_SMEM);

    // fused Q/K/V projections (Q epilogue scale = 0.125*log2e)
    gemm_qkv_kernel<<<dim3(18, S_ / 128, B_), 256, GEMM_SMEM>>>(
        hs_hi, wt_hi, bq, bk, bv,
        (__half*)pq_hi, (__half*)pk_hi, (__half*)pv_hi);

    cudaFuncSetAttribute(attn_mma_kernel, cudaFuncAttributeMaxDynamicSharedMemorySize, ATTN_SMEM);
    attn_mma_kernel<<<dim3(S_ / 128, NH_, B_), 256, ATTN_SMEM>>>(mask,
        (const __half*)pq_hi, (const __half*)pk_hi, (const __half*)pv_hi,
        (__half*)pctx_hi);

    // O projection: 1-term, f32 output
    gemm_o_kernel<<<dim3(H_ / 128, S_ / 128, B_), 256, GEMM_SMEM>>>(
        (const __half*)pctx_hi, wt_hi + 3 * WT_PER, bo, out);
}

// round 17
// speedup vs baseline: 1.0788x; 1.0072x over previous
#include <cuda_runtime.h>
#include <cuda_fp16.h>
#include <cstdint>

// ---------------- problem constants ----------------
#define B_  32
#define S_  512
#define H_  768
#define NH_ 12
#define DH_ 64
#define EC_ 4
#define EU_ 4
#define CAP_ 8   // int(1.0 * 32 / 4)

#define NELEM (B_ * S_ * H_)
#define LOG2E_ 1.4426950408889634f
#define QSCALE_ (0.125f * LOG2E_)

// ---------------- scratch (static device memory; no allocs) ----------------
__device__ float g_hmean[B_ * H_];
__device__ int   g_eidx[B_];
__device__ int   g_used[8];
__device__ __align__(16) __half g_hs_hi[NELEM];
__device__ __align__(16) __half g_q_hi[NELEM];
__device__ __align__(16) __half g_k_hi[NELEM];
__device__ __align__(16) __half g_v_hi[NELEM];
__device__ __align__(16) __half g_ctx_hi[NELEM];
// expert weights fp16, NATIVE [mat(4)][e(8)][k(768)][n(768)] layout (no transpose)
#define WT_PER (8 * H_ * H_)
__device__ __align__(16) __half g_wt_hi[4 * WT_PER];

// ================= PTX helpers (baseline PTX only) =================
__device__ __forceinline__ uint32_t smem_u32(const void* p) {
    uint32_t a;
    asm("{ .reg .u64 t; cvta.to.shared.u64 t, %1; cvt.u32.u64 %0, t; }" : "=r"(a) : "l"(p));
    return a;
}

__device__ __forceinline__ void cp16(uint32_t saddr, const void* gaddr) {
    asm volatile("cp.async.cg.shared.global [%0], [%1], 16;" :: "r"(saddr), "l"(gaddr));
}
#define CP_COMMIT() asm volatile("cp.async.commit_group;" ::: "memory")
#define CP_WAIT1()  asm volatile("cp.async.wait_group 1;" ::: "memory")
#define CP_WAIT0()  asm volatile("cp.async.wait_group 0;" ::: "memory")

#define LDSM_X4(r, addr) \
    asm volatile("ldmatrix.sync.aligned.m8n8.x4.shared.b16 {%0,%1,%2,%3}, [%4];" \
        : "=r"((r)[0]), "=r"((r)[1]), "=r"((r)[2]), "=r"((r)[3]) : "r"(addr))

#define LDSM_X4_T(r, addr) \
    asm volatile("ldmatrix.sync.aligned.m8n8.x4.trans.shared.b16 {%0,%1,%2,%3}, [%4];" \
        : "=r"((r)[0]), "=r"((r)[1]), "=r"((r)[2]), "=r"((r)[3]) : "r"(addr))

#define MMA_F16(c, a, bb) \
    asm volatile("mma.sync.aligned.m16n8k16.row.col.f32.f16.f16.f32 " \
        "{%0,%1,%2,%3}, {%4,%5,%6,%7}, {%8,%9}, {%0,%1,%2,%3};" \
        : "+f"((c)[0]), "+f"((c)[1]), "+f"((c)[2]), "+f"((c)[3]) \
        : "r"((a)[0]), "r"((a)[1]), "r"((a)[2]), "r"((a)[3]), "r"((bb)[0]), "r"((bb)[1]))

__device__ __forceinline__ uint32_t packh(float lo, float hi) {
    uint32_t r;
    asm("cvt.rn.f16x2.f32 %0, %1, %2;" : "=r"(r) : "f"(hi), "f"(lo));
    return r;
}
__device__ __forceinline__ uint32_t hadd2(uint32_t a, uint32_t b) {
    uint32_t r;
    asm("add.f16x2 %0, %1, %2;" : "=r"(r) : "r"(a), "r"(b));
    return r;
}
__device__ __forceinline__ uint32_t hex2(uint32_t a) {
    uint32_t r;
    asm("ex2.approx.f16x2 %0, %1;" : "=r"(r) : "r"(a));
    return r;
}

// ---------------- 1) mean over sequence + fp16 rounding of hs (fused) ----------------
__global__ void mean_round_kernel(const float* __restrict__ hs, __half* __restrict__ hi) {
    const int b = blockIdx.x;
    const int h = threadIdx.x;                 // 768 threads
    const float* p = hs + (size_t)b * S_ * H_ + h;
    __half* q = hi + (size_t)b * S_ * H_ + h;
    float acc = 0.f;
    #pragma unroll 8
    for (int s = 0; s < S_; s++) {
        const float x = p[(size_t)s * H_];
        acc += x;
        q[(size_t)s * H_] = __float2half_rn(x);
    }
    g_hmean[b * H_ + h] = acc * (1.0f / S_);
}

// ---------------- 2) routing + capacity drop (256 threads: 8 per sequence) ----------------
__global__ void route_kernel(const float* __restrict__ Wsc, const float* __restrict__ bsc,
                             const float* __restrict__ Wsu, const float* __restrict__ bsu) {
    __shared__ float pcmax[B_];
    __shared__ int   rcs[B_];
    __shared__ int   rus[B_];
    const int tid = threadIdx.x;
    const int g = tid & 7;
    const int b = tid >> 3;
    if (tid < 8) g_used[tid] = 0;
    {
        float lc[EC_] = {}, lu[EU_] = {};
        for (int h = g; h < H_; h += 8) {
            float x = g_hmean[b * H_ + h];
            #pragma unroll
            for (int e = 0; e < EC_; e++) lc[e] += x * Wsc[h * EC_ + e];
            #pragma unroll
            for (int e = 0; e < EU_; e++) lu[e] += x * Wsu[h * EU_ + e];
        }
        #pragma unroll
        for (int m = 1; m < 8; m <<= 1) {
            #pragma unroll
            for (int e = 0; e < EC_; e++) lc[e] += __shfl_xor_sync(0xffffffffu, lc[e], m);
            #pragma unroll
            for (int e = 0; e < EU_; e++) lu[e] += __shfl_xor_sync(0xffffffffu, lu[e], m);
        }
        if (g == 0) {
            #pragma unroll
            for (int e = 0; e < EC_; e++) lc[e] += bsc[e];
            #pragma unroll
            for (int e = 0; e < EU_; e++) lu[e] += bsu[e];
            float mc = lc[0]; int rc = 0;
            #pragma unroll
            for (int e = 1; e < EC_; e++) if (lc[e] > mc) { mc = lc[e]; rc = e; }
            float sc = 0.f;
            #pragma unroll
            for (int e = 0; e < EC_; e++) sc += __expf(lc[e] - mc);
            float mu = lu[0]; int ru = 0;
            #pragma unroll
            for (int e = 1; e < EU_; e++) if (lu[e] > mu) { mu = lu[e]; ru = e; }
            pcmax[b] = 1.f / sc;
            rcs[b] = rc;
            rus[b] = ru;
        }
    }
    __syncthreads();
    if (tid < B_) {
        const int b2i = tid;
        int rank = 1;
        const float pm = pcmax[b2i];
        const int   rc = rcs[b2i];
        for (int b2 = 0; b2 < B_; b2++) {
            if (b2 == b2i || rcs[b2] != rc) continue;
            if (pcmax[b2] > pm || (pcmax[b2] == pm && b2 < b2i)) rank++;
        }
        const int ei = (rank <= CAP_) ? rc : (EC_ + rus[b2i]);
        g_eidx[b2i] = ei;
        atomicExch(&g_used[ei], 1);
    }
}

// ---------------- prep: pure f32->fp16 convert of used-expert W mats (native layout) ----------
__global__ __launch_bounds__(256) void conv_w4_kernel(
    const float* __restrict__ W0, const float* __restrict__ W1,
    const float* __restrict__ W2, const float* __restrict__ W3,
    __half* __restrict__ th) {
    const int mz = blockIdx.z;                 // 0..31: mat*8 + e
    const int mat = mz >> 3, e = mz & 7;
    if (!g_used[e]) return;
    const float* W = (mat == 0 ? W0 : mat == 1 ? W1 : mat == 2 ? W2 : W3);
    const float4* src = (const float4*)(W + (size_t)e * H_ * H_);
    uint2* dst = (uint2*)(th + (size_t)mat * WT_PER + (size_t)e * H_ * H_);
    const int i = blockIdx.x * 256 + threadIdx.x;
    float4 x = src[i];
    uint2 h;
    h.x = packh(x.x, x.y); h.y = packh(x.z, x.w);
    dst[i] = h;
}

// ================ core GEMM tile routine (1-term fp16, 3-stage BK=64, CTA 128x128) ================
// 8 warps as 2(M) x 4(N); warp tile 64x32. A tile [128 m][64 k] rows 144B;
// B tile k-major [64 k][128 n] rows 272B, consumed via LDSM.trans.
#define GA_SZ  18432                 // 128 * 144
#define GB_SZ  17408                 // 64 * 272
#define GST    (GA_SZ + GB_SZ)       // 35840
#define GB_OFF GA_SZ
#define KIT    (H_ / 64)             // 12
#define GEMM_SMEM (3 * GST)          // 107520

struct GemmAcc { float a[4][4][4]; };   // [mt(4 x 16rows)][nt(4 x 8cols)][frag]

__device__ __forceinline__ void gemm_tile_body(
    uint32_t sbase, const __half* Ah, const __half* Wh, int tid, GemmAcc& G) {
    const int lane = tid & 31, wid = tid >> 5;
    const int warp_m = (wid & 1) * 64, warp_n = (wid >> 1) * 32;
    const int r8 = lane & 7, g = lane >> 3;

    auto issue = [&](int kc) {
        const uint32_t sb = sbase + (uint32_t)(kc % 3) * GST;
        const int k0 = kc * 64;
        #pragma unroll
        for (int i = 0; i < 4; i++) {
            const int idx = i * 256 + tid;
            const int row = idx >> 3, c = idx & 7;
            cp16(sb + row * 144 + c * 16, Ah + (size_t)row * H_ + k0 + c * 8);
        }
        #pragma unroll
        for (int i = 0; i < 4; i++) {
            const int idx = i * 256 + tid;
            const int row = idx >> 4, c = idx & 15;
            cp16(sb + GB_OFF + row * 272 + c * 16, Wh + (size_t)(k0 + row) * H_ + c * 8);
        }
        CP_COMMIT();
    };

    issue(0);
    issue(1);
    for (int kc = 0; kc < KIT; kc++) {
        if (kc < KIT - 1) { CP_WAIT1(); } else { CP_WAIT0(); }
        __syncthreads();
        if (kc + 2 < KIT) issue(kc + 2);
        const uint32_t sb = sbase + (uint32_t)(kc % 3) * GST;
        #pragma unroll
        for (int ks = 0; ks < 64; ks += 16) {
            uint32_t bh[2][4], ah[4][4];
            #pragma unroll
            for (int p = 0; p < 2; p++) {
                const uint32_t addr = sb + GB_OFF +
                    (uint32_t)((ks + (g & 1) * 8 + r8) * 272 +
                               (warp_n + p * 16 + (g >> 1) * 8) * 2);
                LDSM_X4_T(bh[p], addr);
            }
            #pragma unroll
            for (int mt = 0; mt < 4; mt++) {
                const uint32_t addr = sb +
                    (uint32_t)((warp_m + mt * 16 + (lane & 15)) * 144 +
                               (ks + (lane >> 4) * 8) * 2);
                LDSM_X4(ah[mt], addr);
            }
            #pragma unroll
            for (int mt = 0; mt < 4; mt++) {
                #pragma unroll
                for (int nt = 0; nt < 4; nt++) {
                    uint32_t* bhp = &bh[nt >> 1][(nt & 1) * 2];
                    MMA_F16(G.a[mt][nt], ah[mt], bhp);
                }
            }
        }
    }
}

// ---------------- fused QKV projection: 3 mats in one launch ----------------
__global__ __launch_bounds__(256, 2) void gemm_qkv_kernel(
    const __half* __restrict__ a_hi, const __half* __restrict__ w_all,
    const float* __restrict__ bq, const float* __restrict__ bk, const float* __restrict__ bv,
    __half* __restrict__ qout, __half* __restrict__ kout, __half* __restrict__ vout) {
    extern __shared__ char smem[];
    const uint32_t sbase = smem_u32(smem);
    const int tid = threadIdx.x;
    const int lane = tid & 31, wid = tid >> 5;
    const int mat = blockIdx.x / 6;
    const int n0  = (blockIdx.x % 6) * 128;
    const int b  = blockIdx.z;
    const int e  = g_eidx[b];
    const int bm = blockIdx.y * 128;
    const int warp_m = (wid & 1) * 64, warp_n = (wid >> 1) * 32;

    const float* bias = (mat == 0) ? bq : (mat == 1) ? bk : bv;
    __half* outp      = (mat == 0) ? qout : (mat == 1) ? kout : vout;
    const float scale = (mat == 0) ? QSCALE_ : 1.0f;

    const __half* Ah = a_hi + ((size_t)b * S_ + bm) * H_;
    const __half* Wh = w_all + (size_t)mat * WT_PER + (size_t)e * H_ * H_ + n0;

    GemmAcc G = {};
    gemm_tile_body(sbase, Ah, Wh, tid, G);

    const int col_c = n0 + warp_n + (lane & 3) * 2;
    #pragma unroll
    for (int mt = 0; mt < 4; mt++) {
        const int r0 = bm + warp_m + mt * 16 + (lane >> 2);
        #pragma unroll
        for (int nt = 0; nt < 4; nt++) {
            const int cc = col_c + nt * 8;
            const float b0 = bias[e * H_ + cc];
            const float b1 = bias[e * H_ + cc + 1];
            float v00 = (G.a[mt][nt][0] + b0) * scale, v01 = (G.a[mt][nt][1] + b1) * scale;
            float v10 = (G.a[mt][nt][2] + b0) * scale, v11 = (G.a[mt][nt][3] + b1) * scale;
            const size_t o0 = ((size_t)b * S_ + r0) * H_ + cc;
            const size_t o1 = ((size_t)b * S_ + r0 + 8) * H_ + cc;
            *(uint32_t*)(outp + o0) = packh(v00, v01);
            *(uint32_t*)(outp + o1) = packh(v10, v11);
        }
    }
}

// ---------------- O projection (1-term, f32 out) ----------------
__global__ __launch_bounds__(256, 2) void gemm_o_kernel(
    const __half* __restrict__ a_hi, const __half* __restrict__ w_hi,
    const float* __restrict__ bias, float* __restrict__ C) {
    extern __shared__ char smem[];
    const uint32_t sbase = smem_u32(smem);
    const int tid = threadIdx.x;
    const int lane = tid & 31, wid = tid >> 5;
    const int b  = blockIdx.z;
    const int e  = g_eidx[b];
    const int n0 = blockIdx.x * 128;
    const int bm = blockIdx.y * 128;
    const int warp_m = (wid & 1) * 64, warp_n = (wid >> 1) * 32;

    const __half* Ah = a_hi + ((size_t)b * S_ + bm) * H_;
    const __half* Wh = w_hi + (size_t)e * H_ * H_ + n0;

    GemmAcc G = {};
    gemm_tile_body(sbase, Ah, Wh, tid, G);

    float* Cb = C + (size_t)b * S_ * H_;
    const int col_c = n0 + warp_n + (lane & 3) * 2;
    #pragma unroll
    for (int mt = 0; mt < 4; mt++) {
        const int r0 = bm + warp_m + mt * 16 + (lane >> 2);
        #pragma unroll
        for (int nt = 0; nt < 4; nt++) {
            const int cc = col_c + nt * 8;
            const float b0 = bias[e * H_ + cc];
            const float b1 = bias[e * H_ + cc + 1];
            *(float2*)(Cb + (size_t)r0 * H_ + cc) =
                make_float2(G.a[mt][nt][0] + b0, G.a[mt][nt][1] + b1);
            *(float2*)(Cb + (size_t)(r0 + 8) * H_ + cc) =
                make_float2(G.a[mt][nt][2] + b0, G.a[mt][nt][3] + b1);
        }
    }
}

// ---------------- flash attention via mma.sync (f16x2 softmax + ones-MMA row sums) -----------
// Q pre-scaled by 0.125*log2e. Mask pre-scaled by log2e, stored as f16x2 pairs.
// p = ex2.f16x2(cvt(c) + mask2) -> directly the A-fragment of PV.
// Row sums l accumulated by one extra MMA per np with B = ones (every col = full row sum).
#define AT_STR 144                   // bytes per smem row
#define AT_TILE (128 * AT_STR)       // 18432 B
#define AT_QH 0
#define AT_KV AT_TILE                // per-buf: Kh, Vh
#define AT_BUF (2 * AT_TILE)
#define AT_MASK (AT_KV + 2 * AT_BUF) // 92160
#define ATTN_SMEM (AT_MASK + 1024)   // 93184 (mask: 256 half2 = 1KB)

__global__ __launch_bounds__(256, 2) void attn_mma_kernel(
    const float* __restrict__ mask,
    const __half* __restrict__ qh_g,
    const __half* __restrict__ kh_g, const __half* __restrict__ vh_g,
    __half* __restrict__ ctx_hi) {
    extern __shared__ char smc[];
    const uint32_t sb = smem_u32(smc);
    const int tid = threadIdx.x;
    const int lane = tid & 31, w = tid >> 5;
    const int q0 = blockIdx.x * 128;
    const int hh = blockIdx.y;
    const int b  = blockIdx.z;
    const int r8 = lane & 7, g = lane >> 3;
    const uint32_t* mask2 = (const uint32_t*)(smc + AT_MASK);

    auto load_q = [&]() {
        #pragma unroll
        for (int i = 0; i < 4; i++) {
            const int idx = i * 256 + tid;
            const int row = idx >> 3, c16 = (idx & 7) * 16, ce = (idx & 7) * 8;
            const size_t ga = ((size_t)b * S_ + q0 + row) * H_ + hh * DH_ + ce;
            cp16(sb + AT_QH + row * AT_STR + c16, qh_g + ga);
        }
    };
    auto load_kv = [&](int t) {
        const uint32_t kb = sb + AT_KV + (t & 1) * AT_BUF;
        #pragma unroll
        for (int i = 0; i < 4; i++) {
            const int idx = i * 256 + tid;
            const int row = idx >> 3, c16 = (idx & 7) * 16, ce = (idx & 7) * 8;
            const size_t ga = ((size_t)b * S_ + t * 128 + row) * H_ + hh * DH_ + ce;
            const uint32_t so = row * AT_STR + c16;
            cp16(kb + so,           kh_g + ga);
            cp16(kb + AT_TILE + so, vh_g + ga);
        }
    };

    load_q(); load_kv(0); CP_COMMIT();
    load_kv(1); CP_COMMIT();
    // mask -> f16x2 pairs scaled by log2e (512 keys = 256 half2)
    if (tid < 128) {
        float4 m = *(const float4*)(mask + (size_t)b * S_ + tid * 4);
        uint2 mm;
        mm.x = packh(m.x * LOG2E_, m.y * LOG2E_);
        mm.y = packh(m.z * LOG2E_, m.w * LOG2E_);
        ((uint2*)(smc + AT_MASK))[tid] = mm;
    }

    const uint32_t ONES2 = 0x3C003C00u;
    uint32_t onesr[2] = {ONES2, ONES2};

    uint32_t qh[4][4];
    float o[8][4] = {};
    float ol[4] = {};                 // row-sum accumulator (every col = full row sum)

    for (int t = 0; t < 4; t++) {
        if (t < 3) { CP_WAIT1(); } else { CP_WAIT0(); }
        __syncthreads();

        if (t == 0) {
            #pragma unroll
            for (int kc = 0; kc < 4; kc++) {
                const uint32_t qa = sb + (uint32_t)((w * 16 + (g & 1) * 8 + r8) * AT_STR +
                                                    (kc * 16 + (g >> 1) * 8) * 2);
                LDSM_X4(qh[kc], qa + AT_QH);
            }
        }

        const uint32_t kb = sb + AT_KV + (t & 1) * AT_BUF;
        #pragma unroll
        for (int np = 0; np < 8; np++) {
            float c0[4] = {}, c1[4] = {};
            #pragma unroll
            for (int kc = 0; kc < 4; kc++) {
                uint32_t bh[4];
                const uint32_t ka = kb + (uint32_t)((np * 16 + (g >> 1) * 8 + r8) * AT_STR +
                                                    (kc * 16 + (g & 1) * 8) * 2);
                LDSM_X4(bh, ka);
                MMA_F16(c0, qh[kc], bh);
                MMA_F16(c1, qh[kc], bh + 2);
            }
            uint32_t vf[4][4];
            #pragma unroll
            for (int nv = 0; nv < 4; nv++) {
                const uint32_t va = kb + AT_TILE +
                    (uint32_t)((np * 16 + (g & 1) * 8 + r8) * AT_STR +
                               (nv * 16 + (g >> 1) * 8) * 2);
                LDSM_X4_T(vf[nv], va);
            }
            // f16x2 softmax numerator: p = 2^(c + mask)
            const int pi = t * 64 + np * 8 + (lane & 3);
            const uint32_t mkA = mask2[pi], mkC = mask2[pi + 4];
            uint32_t ph[4];
            ph[0] = hex2(hadd2(packh(c0[0], c0[1]), mkA));
            ph[1] = hex2(hadd2(packh(c0[2], c0[3]), mkA));
            ph[2] = hex2(hadd2(packh(c1[0], c1[1]), mkC));
            ph[3] = hex2(hadd2(packh(c1[2], c1[3]), mkC));
            // PV + row-sum MMA
            #pragma unroll
            for (int nv = 0; nv < 4; nv++) {
                MMA_F16(o[2*nv],   ph, vf[nv]);
                MMA_F16(o[2*nv+1], ph, vf[nv] + 2);
            }
            MMA_F16(ol, ph, onesr);
        }
        __syncthreads();
        if (t < 2) { load_kv(t + 2); CP_COMMIT(); }
    }

    // ---- epilogue (no shuffles: ol already holds full row sums) ----
    const float inv1 = 1.f / ol[0], inv2 = 1.f / ol[2];
    const int row1 = q0 + w * 16 + (lane >> 2);
    #pragma unroll
    for (int nt = 0; nt < 8; nt++) {
        const int dh = hh * DH_ + nt * 8 + 2 * (lane & 3);
        const size_t o0 = ((size_t)b * S_ + row1) * H_ + dh;
        const size_t o1 = ((size_t)b * S_ + row1 + 8) * H_ + dh;
        *(uint32_t*)(ctx_hi + o0) = packh(o[nt][0] * inv1, o[nt][1] * inv1);
        *(uint32_t*)(ctx_hi + o1) = packh(o[nt][2] * inv2, o[nt][3] * inv2);
    }
}

// ---------------- launch ----------------
extern "C" void kernel_launch(void* const* d_in, const int* in_sizes, int n_in,
                              void* d_out, int out_size) {
    const float* hs   = (const float*)d_in[0];
    const float* mask = (const float*)d_in[1];
    const float* Wq = (const float*)d_in[2];
    const float* bq = (const float*)d_in[3];
    const float* Wk = (const float*)d_in[4];
    const float* bk = (const float*)d_in[5];
    const float* Wv = (const float*)d_in[6];
    const float* bv = (const float*)d_in[7];
    const float* Wo = (const float*)d_in[8];
    const float* bo = (const float*)d_in[9];
    const float* Wsc = (const float*)d_in[10];
    const float* bsc = (const float*)d_in[11];
    const float* Wsu = (const float*)d_in[12];
    const float* bsu = (const float*)d_in[13];
    float* out = (float*)d_out;

    void *phs_hi, *pq_hi, *pk_hi, *pv_hi, *pctx_hi, *pwt_hi;
    cudaGetSymbolAddress(&phs_hi, g_hs_hi);
    cudaGetSymbolAddress(&pq_hi, g_q_hi);
    cudaGetSymbolAddress(&pk_hi, g_k_hi);
    cudaGetSymbolAddress(&pv_hi, g_v_hi);
    cudaGetSymbolAddress(&pctx_hi, g_ctx_hi);
    cudaGetSymbolAddress(&pwt_hi, g_wt_hi);
    __half* hs_hi = (__half*)phs_hi;
    __half* wt_hi = (__half*)pwt_hi;

    mean_round_kernel<<<B_, H_>>>(hs, hs_hi);
    route_kernel<<<1, 256>>>(Wsc, bsc, Wsu, bsu);
    conv_w4_kernel<<<dim3(H_ * H_ / 4 / 256, 1, 32), 256>>>(Wq, Wk, Wv, Wo, wt_hi);

    cudaFuncSetAttribute(gemm_qkv_kernel, cudaFuncAttributeMaxDynamicSharedMemorySize, GEMM_SMEM);
    cudaFuncSetAttribute(gemm_o_kernel,   cudaFuncAttributeMaxDynamicSharedMemorySize, GEMM_SMEM);

    // fused Q/K/V projections (Q epilogue scale = 0.125*log2e)
    gemm_qkv_kernel<<<dim3(18, S_ / 128, B_), 256, GEMM_SMEM>>>(
        hs_hi, wt_hi, bq, bk, bv,
        (__half*)pq_hi, (__half*)pk_hi, (__half*)pv_hi);

    cudaFuncSetAttribute(attn_mma_kernel, cudaFuncAttributeMaxDynamicSharedMemorySize, ATTN_SMEM);
    attn_mma_kernel<<<dim3(S_ / 128, NH_, B_), 256, ATTN_SMEM>>>(mask,
        (const __half*)pq_hi, (const __half*)pk_hi, (const __half*)pv_hi,
        (__half*)pctx_hi);

    // O projection: 1-term, f32 output
    gemm_o_kernel<<<dim3(H_ / 128, S_ / 128, B_), 256, GEMM_SMEM>>>(
        (const __half*)pctx_hi, wt_hi + 3 * WT_PER, bo, out);
}